// round 14
// baseline (speedup 1.0000x reference)
#include <cuda_runtime.h>
#include <cuda_fp16.h>
#include <string.h>

#define NN 100000
#define EE 1600000
#define IN_DIM 128
#define HID 32
#define HEADS 4
#define OUT_DIM 40
#define NEG_SLOPE 0.2f

#define G1_ROWS 128
#define A_STRIDE 136
#define G1_SMEM ((G1_ROWS*A_STRIDE + IN_DIM*A_STRIDE) * 2)   // 69632 B
#define G2_ROWS 128
#define B2_STRIDE 48
#define G2_SMEM ((G2_ROWS*A_STRIDE + IN_DIM*B2_STRIDE) * 2)  // 47104 B
#define SCAN_B 1024
#define NB ((NN + SCAN_B - 1) / SCAN_B)   // 98
#define AGG_BLOCKS 592
#define NODE_BATCH 8

typedef unsigned long long ull;
typedef unsigned int uint;

// ---------------- f32x2 packed-math helpers (sm_103a) ----------------
__device__ __forceinline__ ull pack2(float a, float b) {
    ull r; asm("mov.b64 %0,{%1,%2};" : "=l"(r) : "f"(a), "f"(b)); return r;
}
__device__ __forceinline__ void unpack2(ull p, float& a, float& b) {
    asm("mov.b64 {%0,%1},%2;" : "=f"(a), "=f"(b) : "l"(p));
}
__device__ __forceinline__ void ffma2(ull& acc, ull a, ull b) {
    asm("fma.rn.f32x2 %0,%1,%2,%0;" : "+l"(acc) : "l"(a), "l"(b));
}
// ---------------- fp16 bit-cast helpers ----------------
__device__ __forceinline__ uint f2_to_h2u(float a, float b) {
    __half2 h = __floats2half2_rn(a, b);
    uint u; memcpy(&u, &h, 4); return u;
}
__device__ __forceinline__ float2 h2u_to_f2(uint u) {
    __half2 h; memcpy(&h, &u, 4);
    return __half22float2(h);
}

// ---------------- scratch (device globals: allocation-free) ----------------
__device__ __half g_feat1h[NN * IN_DIM];
__device__ float  g_el1[NN * HEADS];
__device__ float  g_er1[NN * HEADS];
__device__ __half g_h1h[NN * IN_DIM];
__device__ __half g_feat2h[NN * OUT_DIM];
__device__ float  g_el2[NN];
__device__ float  g_er2[NN];
__device__ __half g_W1h[IN_DIM * IN_DIM];
__device__ int    g_deg[NN];
__device__ int    g_rank[EE];
__device__ int    g_rowptr[NN + 1];
__device__ int    g_esrc[EE];
__device__ int    g_bsum[128];
__device__ int    g_boff[128];
__device__ int    g_ctr1, g_ctr2;

// ---------------- zero deg + work counters ----------------
__global__ void zero_kernel() {
    int i = blockIdx.x * blockDim.x + threadIdx.x;
    if (i < NN) g_deg[i] = 0;
    if (i == 0) { g_ctr1 = 0; g_ctr2 = 0; }
}

// ---------------- W1 fp32 -> fp16 (once per launch) ----------------
__global__ void w1cvt_kernel(const float* __restrict__ W1) {
    int i = blockIdx.x * blockDim.x + threadIdx.x;
    if (i < IN_DIM * IN_DIM / 2) {
        float2 f = ((const float2*)W1)[i];
        ((__half2*)g_W1h)[i] = __floats2half2_rn(f.x, f.y);
    }
}

// ---- GEMM1 on tensor cores: 128-row tile, 512 thr, fused el1/er1, fp16 out ----
__global__ __launch_bounds__(512) void gemm1_kernel(const float* __restrict__ h,
                                                    const float* __restrict__ al1,
                                                    const float* __restrict__ ar1) {
    extern __shared__ __half smh[];
    __half* As = smh;                          // [128][A_STRIDE]
    __half* Ws = smh + G1_ROWS * A_STRIDE;     // [128][A_STRIDE]
    int t = threadIdx.x;
    int row0 = blockIdx.x * G1_ROWS;

    for (int i = t; i < IN_DIM * IN_DIM / 8; i += 512) {
        int r = i >> 4, c8 = i & 15;
        uint4 v = ((const uint4*)g_W1h)[i];
        *(uint4*)(Ws + r * A_STRIDE + c8 * 8) = v;
    }
    const float4* H4 = (const float4*)h;
    for (int i = t; i < G1_ROWS * IN_DIM / 4; i += 512) {
        int r = i >> 5, c4 = i & 31;
        int g = row0 + r;
        float4 f = (g < NN) ? H4[g * 32 + c4] : make_float4(0.f, 0.f, 0.f, 0.f);
        uint2 v;
        v.x = f2_to_h2u(f.x, f.y);
        v.y = f2_to_h2u(f.z, f.w);
        *(uint2*)(As + r * A_STRIDE + c4 * 4) = v;
    }
    __syncthreads();

    int w = t >> 5, lane = t & 31;
    int rw = (w & 7) * 16;
    int ch = (w >> 3) * 64;

    uint a_base = (uint)__cvta_generic_to_shared(
        As + (rw + (lane & 15)) * A_STRIDE + ((lane >> 4) * 8));
    uint b_base = (uint)__cvta_generic_to_shared(
        Ws + (lane & 15) * A_STRIDE + ch + ((lane >> 4) * 8));

    float acc[8][4];
    #pragma unroll
    for (int j = 0; j < 8; ++j)
        #pragma unroll
        for (int c = 0; c < 4; ++c) acc[j][c] = 0.f;

    #pragma unroll
    for (int kb = 0; kb < 8; ++kb) {
        uint a0, a1, a2, a3;
        asm volatile("ldmatrix.sync.aligned.m8n8.x4.shared.b16 {%0,%1,%2,%3}, [%4];"
                     : "=r"(a0), "=r"(a1), "=r"(a2), "=r"(a3)
                     : "r"(a_base + kb * 32));
        #pragma unroll
        for (int p = 0; p < 4; ++p) {
            uint b0, b1, b2, b3;
            asm volatile("ldmatrix.sync.aligned.m8n8.x4.trans.shared.b16 {%0,%1,%2,%3}, [%4];"
                         : "=r"(b0), "=r"(b1), "=r"(b2), "=r"(b3)
                         : "r"(b_base + kb * 16 * A_STRIDE * 2 + p * 32));
            asm volatile("mma.sync.aligned.m16n8k16.row.col.f32.f16.f16.f32 "
                         "{%0,%1,%2,%3}, {%4,%5,%6,%7}, {%8,%9}, {%0,%1,%2,%3};"
                         : "+f"(acc[2*p][0]), "+f"(acc[2*p][1]), "+f"(acc[2*p][2]), "+f"(acc[2*p][3])
                         : "r"(a0), "r"(a1), "r"(a2), "r"(a3), "r"(b0), "r"(b1));
            asm volatile("mma.sync.aligned.m16n8k16.row.col.f32.f16.f16.f32 "
                         "{%0,%1,%2,%3}, {%4,%5,%6,%7}, {%8,%9}, {%0,%1,%2,%3};"
                         : "+f"(acc[2*p+1][0]), "+f"(acc[2*p+1][1]), "+f"(acc[2*p+1][2]), "+f"(acc[2*p+1][3])
                         : "r"(a0), "r"(a1), "r"(a2), "r"(a3), "r"(b2), "r"(b3));
        }
    }

    int g0 = lane >> 2, quad = lane & 3;
    int r0g = row0 + rw + g0;
    int r1g = r0g + 8;
    int h0 = (w >> 3) * 2;

    float pe[2][2] = {{0.f, 0.f}, {0.f, 0.f}};
    float pr[2][2] = {{0.f, 0.f}, {0.f, 0.f}};

    #pragma unroll
    for (int j = 0; j < 8; ++j) {
        int n0 = ch + j * 8 + quad * 2;
        float2 av = *(const float2*)(al1 + n0);
        float2 rv = *(const float2*)(ar1 + n0);
        if (r0g < NN) ((uint*)g_feat1h)[(r0g * IN_DIM + n0) >> 1] = f2_to_h2u(acc[j][0], acc[j][1]);
        if (r1g < NN) ((uint*)g_feat1h)[(r1g * IN_DIM + n0) >> 1] = f2_to_h2u(acc[j][2], acc[j][3]);
        int hi = j >> 2;
        pe[hi][0] += acc[j][0] * av.x + acc[j][1] * av.y;
        pe[hi][1] += acc[j][2] * av.x + acc[j][3] * av.y;
        pr[hi][0] += acc[j][0] * rv.x + acc[j][1] * rv.y;
        pr[hi][1] += acc[j][2] * rv.x + acc[j][3] * rv.y;
    }
    #pragma unroll
    for (int hi = 0; hi < 2; ++hi)
        #pragma unroll
        for (int rr = 0; rr < 2; ++rr) {
            float e = pe[hi][rr], r = pr[hi][rr];
            e += __shfl_xor_sync(0xFFFFFFFFu, e, 1);
            e += __shfl_xor_sync(0xFFFFFFFFu, e, 2);
            r += __shfl_xor_sync(0xFFFFFFFFu, r, 1);
            r += __shfl_xor_sync(0xFFFFFFFFu, r, 2);
            int g = rr ? r1g : r0g;
            if (quad == 0 && g < NN) {
                g_el1[g * 4 + h0 + hi] = e;
                g_er1[g * 4 + h0 + hi] = r;
            }
        }
}

// ---------------- CSR build ----------------
__global__ void hist_kernel(const int* __restrict__ dst) {
    int i = blockIdx.x * blockDim.x + threadIdx.x;
    if (i < EE) g_rank[i] = atomicAdd(&g_deg[dst[i]], 1);
}

__global__ void scan1_kernel() {
    __shared__ int ws[32];
    int t = threadIdx.x;
    int lane = t & 31, wp = t >> 5;
    int i = blockIdx.x * SCAN_B + t;
    int v = (i < NN) ? g_deg[i] : 0;
    int x = v;
    #pragma unroll
    for (int off = 1; off < 32; off <<= 1) {
        int y = __shfl_up_sync(0xFFFFFFFFu, x, off);
        if (lane >= off) x += y;
    }
    if (lane == 31) ws[wp] = x;
    __syncthreads();
    if (wp == 0) {
        int o = ws[lane];
        int s = o;
        #pragma unroll
        for (int off = 1; off < 32; off <<= 1) {
            int y = __shfl_up_sync(0xFFFFFFFFu, s, off);
            if (lane >= off) s += y;
        }
        ws[lane] = s - o;
    }
    __syncthreads();
    int base = ws[wp];
    if (i < NN) g_rowptr[i] = x - v + base;
    if (t == SCAN_B - 1) g_bsum[blockIdx.x] = x + base;
}

__global__ void scan2_kernel() {
    int t = threadIdx.x;
    int lane = t & 31, wp = t >> 5;
    int v = (t < NB) ? g_bsum[t] : 0;
    int x = v;
    #pragma unroll
    for (int off = 1; off < 32; off <<= 1) {
        int y = __shfl_up_sync(0xFFFFFFFFu, x, off);
        if (lane >= off) x += y;
    }
    __shared__ int wsum[4];
    if (lane == 31) wsum[wp] = x;
    __syncthreads();
    int add = 0;
    for (int w = 0; w < wp; ++w) add += wsum[w];
    if (t < NB) g_boff[t] = x - v + add;
}

__global__ void scan3_kernel() {
    int i = blockIdx.x * SCAN_B + threadIdx.x;
    if (i < NN) g_rowptr[i] += g_boff[blockIdx.x];
    if (i == 0) g_rowptr[NN] = EE;
}

__global__ void scatter_kernel(const int* __restrict__ src, const int* __restrict__ dst) {
    int i = blockIdx.x * blockDim.x + threadIdx.x;
    if (i < EE) {
        int d = dst[i];
        g_esrc[g_rowptr[d] + g_rank[i]] = src[i];
    }
}

// ------- layer-1 aggregation: persistent warps, batched work-stealing -------
__global__ __launch_bounds__(256) void agg1_kernel(const float* __restrict__ b1) {
    int l = threadIdx.x & 31;
    int hh = l >> 3;
    const uint2* f2 = (const uint2*)g_feat1h;
    float4 bb = ((const float4*)b1)[l];

    for (;;) {
        int base;
        if (l == 0) base = atomicAdd(&g_ctr1, NODE_BATCH);
        base = __shfl_sync(0xFFFFFFFFu, base, 0);
        if (base >= NN) return;
        int nend = min(base + NODE_BATCH, NN);

        for (int n = base; n < nend; ++n) {
            float erh = g_er1[n * 4 + hh];
            int s0 = g_rowptr[n], s1 = g_rowptr[n + 1];

            ull aA0 = 0, aA1 = 0, aB0 = 0, aB1 = 0;
            float dsA = 0.f, dsB = 0.f;

            int i = s0;
            for (; i + 4 <= s1; i += 4) {
                int sa = g_esrc[i];
                int sb = g_esrc[i + 1];
                int sc = g_esrc[i + 2];
                int sd = g_esrc[i + 3];
                float ea = g_el1[sa * 4 + hh] + erh;
                float eb = g_el1[sb * 4 + hh] + erh;
                float ec = g_el1[sc * 4 + hh] + erh;
                float ed = g_el1[sd * 4 + hh] + erh;
                uint2 fa = f2[sa * 32 + l];
                uint2 fb = f2[sb * 32 + l];
                uint2 fc = f2[sc * 32 + l];
                uint2 fd = f2[sd * 32 + l];
                ea = fmaxf(ea, NEG_SLOPE * ea);
                eb = fmaxf(eb, NEG_SLOPE * eb);
                ec = fmaxf(ec, NEG_SLOPE * ec);
                ed = fmaxf(ed, NEG_SLOPE * ed);
                float wa = __expf(ea), wb = __expf(eb);
                float wc = __expf(ec), wd = __expf(ed);
                float2 fa0 = h2u_to_f2(fa.x), fa1 = h2u_to_f2(fa.y);
                float2 fb0 = h2u_to_f2(fb.x), fb1 = h2u_to_f2(fb.y);
                float2 fc0 = h2u_to_f2(fc.x), fc1 = h2u_to_f2(fc.y);
                float2 fd0 = h2u_to_f2(fd.x), fd1 = h2u_to_f2(fd.y);
                ull wa2 = pack2(wa, wa), wb2 = pack2(wb, wb);
                ull wc2 = pack2(wc, wc), wd2 = pack2(wd, wd);
                ffma2(aA0, wa2, pack2(fa0.x, fa0.y)); ffma2(aA1, wa2, pack2(fa1.x, fa1.y));
                ffma2(aB0, wb2, pack2(fb0.x, fb0.y)); ffma2(aB1, wb2, pack2(fb1.x, fb1.y));
                ffma2(aA0, wc2, pack2(fc0.x, fc0.y)); ffma2(aA1, wc2, pack2(fc1.x, fc1.y));
                ffma2(aB0, wd2, pack2(fd0.x, fd0.y)); ffma2(aB1, wd2, pack2(fd1.x, fd1.y));
                dsA += wa + wc; dsB += wb + wd;
            }
            for (; i < s1; ++i) {
                int sa = g_esrc[i];
                float ea = g_el1[sa * 4 + hh] + erh;
                ea = fmaxf(ea, NEG_SLOPE * ea);
                float wa = __expf(ea);
                uint2 fa = f2[sa * 32 + l];
                float2 fa0 = h2u_to_f2(fa.x), fa1 = h2u_to_f2(fa.y);
                ull wa2 = pack2(wa, wa);
                ffma2(aA0, wa2, pack2(fa0.x, fa0.y));
                ffma2(aA1, wa2, pack2(fa1.x, fa1.y));
                dsA += wa;
            }

            float inv = 1.0f / fmaxf(dsA + dsB, 1e-9f);
            float xA, yA, xB, yB, zA, wA, zB, wB;
            unpack2(aA0, xA, yA); unpack2(aB0, xB, yB);
            unpack2(aA1, zA, wA); unpack2(aB1, zB, wB);
            float o0 = fmaxf((xA + xB) * inv + bb.x, 0.f);
            float o1 = fmaxf((yA + yB) * inv + bb.y, 0.f);
            float o2 = fmaxf((zA + zB) * inv + bb.z, 0.f);
            float o3 = fmaxf((wA + wB) * inv + bb.w, 0.f);
            uint2 v;
            v.x = f2_to_h2u(o0, o1);
            v.y = f2_to_h2u(o2, o3);
            ((uint2*)g_h1h)[n * 32 + l] = v;
        }
    }
}

// ------- GEMM2 on tensor cores: 128-row tile, fused el2/er2, fp16 out -------
__global__ __launch_bounds__(256) void gemm2_kernel(const float* __restrict__ W2,
                                                    const float* __restrict__ al2,
                                                    const float* __restrict__ ar2) {
    extern __shared__ __half smh[];
    __half* As = smh;
    __half* Bs = smh + G2_ROWS * A_STRIDE;
    int t = threadIdx.x;
    int row0 = blockIdx.x * G2_ROWS;

    for (int i = t; i < G2_ROWS * IN_DIM / 8; i += 256) {
        int r = i >> 4, c8 = i & 15;
        int g = row0 + r;
        uint4 v = (g < NN) ? ((const uint4*)g_h1h)[g * 16 + c8]
                           : make_uint4(0u, 0u, 0u, 0u);
        *(uint4*)(As + r * A_STRIDE + c8 * 8) = v;
    }
    for (int i = t; i < IN_DIM * OUT_DIM; i += 256) {
        int r = i / OUT_DIM, c = i - r * OUT_DIM;
        Bs[r * B2_STRIDE + c] = __float2half_rn(W2[i]);
    }
    for (int i = t; i < IN_DIM * 8; i += 256) {
        int r = i >> 3, c = i & 7;
        Bs[r * B2_STRIDE + OUT_DIM + c] = __float2half_rn(0.f);
    }
    __syncthreads();

    int w = t >> 5, lane = t & 31;
    int rw = w * 16;

    uint a_base = (uint)__cvta_generic_to_shared(
        As + (rw + (lane & 15)) * A_STRIDE + ((lane >> 4) * 8));
    uint b_base = (uint)__cvta_generic_to_shared(
        Bs + (lane & 15) * B2_STRIDE + ((lane >> 4) * 8));

    float acc[6][4];
    #pragma unroll
    for (int j = 0; j < 6; ++j)
        #pragma unroll
        for (int c = 0; c < 4; ++c) acc[j][c] = 0.f;

    #pragma unroll
    for (int kb = 0; kb < 8; ++kb) {
        uint a0, a1, a2, a3;
        asm volatile("ldmatrix.sync.aligned.m8n8.x4.shared.b16 {%0,%1,%2,%3}, [%4];"
                     : "=r"(a0), "=r"(a1), "=r"(a2), "=r"(a3)
                     : "r"(a_base + kb * 32));
        #pragma unroll
        for (int p = 0; p < 3; ++p) {
            uint b0, b1, b2, b3;
            asm volatile("ldmatrix.sync.aligned.m8n8.x4.trans.shared.b16 {%0,%1,%2,%3}, [%4];"
                         : "=r"(b0), "=r"(b1), "=r"(b2), "=r"(b3)
                         : "r"(b_base + kb * 16 * B2_STRIDE * 2 + p * 32));
            asm volatile("mma.sync.aligned.m16n8k16.row.col.f32.f16.f16.f32 "
                         "{%0,%1,%2,%3}, {%4,%5,%6,%7}, {%8,%9}, {%0,%1,%2,%3};"
                         : "+f"(acc[2*p][0]), "+f"(acc[2*p][1]), "+f"(acc[2*p][2]), "+f"(acc[2*p][3])
                         : "r"(a0), "r"(a1), "r"(a2), "r"(a3), "r"(b0), "r"(b1));
            asm volatile("mma.sync.aligned.m16n8k16.row.col.f32.f16.f16.f32 "
                         "{%0,%1,%2,%3}, {%4,%5,%6,%7}, {%8,%9}, {%0,%1,%2,%3};"
                         : "+f"(acc[2*p+1][0]), "+f"(acc[2*p+1][1]), "+f"(acc[2*p+1][2]), "+f"(acc[2*p+1][3])
                         : "r"(a0), "r"(a1), "r"(a2), "r"(a3), "r"(b2), "r"(b3));
        }
    }

    int g0 = lane >> 2, quad = lane & 3;
    int r0g = row0 + rw + g0;
    int r1g = r0g + 8;

    float p0 = 0.f, p1 = 0.f, q0 = 0.f, q1 = 0.f;
    #pragma unroll
    for (int j = 0; j < 5; ++j) {
        int n0 = j * 8 + quad * 2;
        float2 av = *(const float2*)(al2 + n0);
        float2 rv = *(const float2*)(ar2 + n0);
        if (r0g < NN) ((uint*)g_feat2h)[(r0g * OUT_DIM + n0) >> 1] = f2_to_h2u(acc[j][0], acc[j][1]);
        if (r1g < NN) ((uint*)g_feat2h)[(r1g * OUT_DIM + n0) >> 1] = f2_to_h2u(acc[j][2], acc[j][3]);
        p0 += acc[j][0] * av.x + acc[j][1] * av.y;
        p1 += acc[j][2] * av.x + acc[j][3] * av.y;
        q0 += acc[j][0] * rv.x + acc[j][1] * rv.y;
        q1 += acc[j][2] * rv.x + acc[j][3] * rv.y;
    }
    #pragma unroll
    for (int off = 1; off <= 2; off <<= 1) {
        p0 += __shfl_xor_sync(0xFFFFFFFFu, p0, off);
        p1 += __shfl_xor_sync(0xFFFFFFFFu, p1, off);
        q0 += __shfl_xor_sync(0xFFFFFFFFu, q0, off);
        q1 += __shfl_xor_sync(0xFFFFFFFFu, q1, off);
    }
    if (quad == 0) {
        if (r0g < NN) { g_el2[r0g] = p0; g_er2[r0g] = q0; }
        if (r1g < NN) { g_el2[r1g] = p1; g_er2[r1g] = q1; }
    }
}

// ------- layer-2 aggregation: persistent warps, batched work-stealing -------
__global__ __launch_bounds__(256) void agg2_kernel(const float* __restrict__ b2, float* __restrict__ out) {
    int l = threadIdx.x & 31;
    int lc = (l < 20) ? l : 19;
    const uint* f2 = (const uint*)g_feat2h;
    float b20 = (l < 20) ? b2[2 * l] : 0.f;
    float b21 = (l < 20) ? b2[2 * l + 1] : 0.f;

    for (;;) {
        int base;
        if (l == 0) base = atomicAdd(&g_ctr2, NODE_BATCH);
        base = __shfl_sync(0xFFFFFFFFu, base, 0);
        if (base >= NN) return;
        int nend = min(base + NODE_BATCH, NN);

        for (int n = base; n < nend; ++n) {
            float er = g_er2[n];
            int s0 = g_rowptr[n], s1 = g_rowptr[n + 1];

            ull aA = 0, aB = 0;
            float dsA = 0.f, dsB = 0.f;

            int i = s0;
            for (; i + 4 <= s1; i += 4) {
                int sa = g_esrc[i];
                int sb = g_esrc[i + 1];
                int sc = g_esrc[i + 2];
                int sd = g_esrc[i + 3];
                float ea = g_el2[sa] + er;
                float eb = g_el2[sb] + er;
                float ec = g_el2[sc] + er;
                float ed = g_el2[sd] + er;
                uint fa = f2[sa * 20 + lc];
                uint fb = f2[sb * 20 + lc];
                uint fc = f2[sc * 20 + lc];
                uint fd = f2[sd * 20 + lc];
                ea = fmaxf(ea, NEG_SLOPE * ea);
                eb = fmaxf(eb, NEG_SLOPE * eb);
                ec = fmaxf(ec, NEG_SLOPE * ec);
                ed = fmaxf(ed, NEG_SLOPE * ed);
                float wa = __expf(ea), wb = __expf(eb);
                float wc = __expf(ec), wd = __expf(ed);
                float2 fav = h2u_to_f2(fa), fbv = h2u_to_f2(fb);
                float2 fcv = h2u_to_f2(fc), fdv = h2u_to_f2(fd);
                ffma2(aA, pack2(wa, wa), pack2(fav.x, fav.y));
                ffma2(aB, pack2(wb, wb), pack2(fbv.x, fbv.y));
                ffma2(aA, pack2(wc, wc), pack2(fcv.x, fcv.y));
                ffma2(aB, pack2(wd, wd), pack2(fdv.x, fdv.y));
                dsA += wa + wc; dsB += wb + wd;
            }
            for (; i < s1; ++i) {
                int sa = g_esrc[i];
                float ea = g_el2[sa] + er;
                ea = fmaxf(ea, NEG_SLOPE * ea);
                float wa = __expf(ea);
                float2 fav = h2u_to_f2(f2[sa * 20 + lc]);
                ffma2(aA, pack2(wa, wa), pack2(fav.x, fav.y));
                dsA += wa;
            }

            if (l < 20) {
                float inv = 1.0f / fmaxf(dsA + dsB, 1e-9f);
                float xa, ya, xb, yb;
                unpack2(aA, xa, ya); unpack2(aB, xb, yb);
                float o0 = (xa + xb) * inv + b20;
                float o1 = (ya + yb) * inv + b21;
                ((ull*)out)[n * 20 + l] = pack2(o0, o1);
            }
        }
    }
}

// ---------------- side stream for CSR/GEMM1 overlap ----------------
namespace {
struct Aux {
    cudaStream_t s2;
    cudaEvent_t fork, join;
    bool ok;
    Aux() : s2(nullptr), fork(nullptr), join(nullptr), ok(false) {
        if (cudaStreamCreateWithFlags(&s2, cudaStreamNonBlocking) != cudaSuccess) return;
        if (cudaEventCreateWithFlags(&fork, cudaEventDisableTiming) != cudaSuccess) return;
        if (cudaEventCreateWithFlags(&join, cudaEventDisableTiming) != cudaSuccess) return;
        ok = true;
    }
};
Aux g_aux;
}

// ---------------- launch ----------------
extern "C" void kernel_launch(void* const* d_in, const int* in_sizes, int n_in,
                              void* d_out, int out_size) {
    const float* h   = (const float*)d_in[0];
    const int*   src = (const int*)  d_in[1];
    const int*   dst = (const int*)  d_in[2];
    const float* W1  = (const float*)d_in[3];
    const float* al1 = (const float*)d_in[4];
    const float* ar1 = (const float*)d_in[5];
    const float* b1  = (const float*)d_in[6];
    const float* W2  = (const float*)d_in[7];
    const float* al2 = (const float*)d_in[8];
    const float* ar2 = (const float*)d_in[9];
    const float* b2  = (const float*)d_in[10];
    float* out = (float*)d_out;

    cudaFuncSetAttribute(gemm1_kernel, cudaFuncAttributeMaxDynamicSharedMemorySize, G1_SMEM);
    cudaFuncSetAttribute(gemm2_kernel, cudaFuncAttributeMaxDynamicSharedMemorySize, G2_SMEM);

    int eblocks = (EE + 255) / 256;
    int g1blocks = (NN + G1_ROWS - 1) / G1_ROWS;
    int g2blocks = (NN + G2_ROWS - 1) / G2_ROWS;

    if (g_aux.ok) {
        cudaEventRecord(g_aux.fork, 0);
        cudaStreamWaitEvent(g_aux.s2, g_aux.fork, 0);
        zero_kernel<<<(NN + 255) / 256, 256, 0, g_aux.s2>>>();            // 1
        hist_kernel<<<eblocks, 256, 0, g_aux.s2>>>(dst);                  // 2
        w1cvt_kernel<<<(IN_DIM * IN_DIM / 2 + 255) / 256, 256>>>(W1);     // 3 (main)
        gemm1_kernel<<<g1blocks, 512, G1_SMEM>>>(h, al1, ar1);            // 4 (main, profiled)
        scan1_kernel<<<NB, SCAN_B, 0, g_aux.s2>>>();                      // 5
        scan2_kernel<<<1, 128, 0, g_aux.s2>>>();                          // 6
        scan3_kernel<<<NB, SCAN_B, 0, g_aux.s2>>>();                      // 7
        scatter_kernel<<<eblocks, 256, 0, g_aux.s2>>>(src, dst);          // 8
        cudaEventRecord(g_aux.join, g_aux.s2);
        cudaStreamWaitEvent(0, g_aux.join, 0);
    } else {
        zero_kernel<<<(NN + 255) / 256, 256>>>();
        hist_kernel<<<eblocks, 256>>>(dst);
        w1cvt_kernel<<<(IN_DIM * IN_DIM / 2 + 255) / 256, 256>>>(W1);
        gemm1_kernel<<<g1blocks, 512, G1_SMEM>>>(h, al1, ar1);
        scan1_kernel<<<NB, SCAN_B>>>();
        scan2_kernel<<<1, 128>>>();
        scan3_kernel<<<NB, SCAN_B>>>();
        scatter_kernel<<<eblocks, 256>>>(src, dst);
    }

    agg1_kernel<<<AGG_BLOCKS, 256>>>(b1);
    gemm2_kernel<<<g2blocks, 256, G2_SMEM>>>(W2, al2, ar2);
    agg2_kernel<<<AGG_BLOCKS, 256>>>(b2, out);
}

// round 15
// speedup vs baseline: 1.1693x; 1.1693x over previous
#include <cuda_runtime.h>
#include <cuda_fp16.h>
#include <string.h>

#define NN 100000
#define EE 1600000
#define IN_DIM 128
#define HID 32
#define HEADS 4
#define OUT_DIM 40
#define NEG_SLOPE 0.2f

#define G1_ROWS 128
#define A_STRIDE 136
#define G1_SMEM ((G1_ROWS*A_STRIDE + IN_DIM*A_STRIDE) * 2)   // 69632 B
#define G2_ROWS 128
#define B2_STRIDE 48
#define G2_SMEM ((G2_ROWS*A_STRIDE + IN_DIM*B2_STRIDE) * 2)  // 47104 B
#define SCAN_B 1024
#define NB ((NN + SCAN_B - 1) / SCAN_B)   // 98

typedef unsigned long long ull;
typedef unsigned int uint;

// ---------------- f32x2 packed-math helpers (sm_103a) ----------------
__device__ __forceinline__ ull pack2(float a, float b) {
    ull r; asm("mov.b64 %0,{%1,%2};" : "=l"(r) : "f"(a), "f"(b)); return r;
}
__device__ __forceinline__ void unpack2(ull p, float& a, float& b) {
    asm("mov.b64 {%0,%1},%2;" : "=f"(a), "=f"(b) : "l"(p));
}
__device__ __forceinline__ void ffma2(ull& acc, ull a, ull b) {
    asm("fma.rn.f32x2 %0,%1,%2,%0;" : "+l"(acc) : "l"(a), "l"(b));
}
// ---------------- fp16 bit-cast helpers ----------------
__device__ __forceinline__ uint f2_to_h2u(float a, float b) {
    __half2 h = __floats2half2_rn(a, b);
    uint u; memcpy(&u, &h, 4); return u;
}
__device__ __forceinline__ float2 h2u_to_f2(uint u) {
    __half2 h; memcpy(&h, &u, 4);
    return __half22float2(h);
}

// ---------------- scratch (device globals: allocation-free) ----------------
__device__ __half g_feat1h[NN * IN_DIM];
__device__ float  g_el1[NN * HEADS];
__device__ float  g_er1[NN * HEADS];
__device__ __half g_h1h[NN * IN_DIM];
__device__ __half g_feat2h[NN * OUT_DIM];
__device__ float  g_el2[NN];
__device__ float  g_er2[NN];
__device__ __half g_W1h[IN_DIM * IN_DIM];
__device__ float  g_ew1[EE * HEADS];       // per-edge per-head softmax weights (layer 1)
__device__ float  g_ew2[EE];               // per-edge weights (layer 2)
__device__ int    g_deg[NN];
__device__ int    g_rank[EE];
__device__ int    g_rowptr[NN + 1];
__device__ int    g_esrc[EE];
__device__ int    g_edst[EE];
__device__ int    g_bsum[128];
__device__ int    g_boff[128];

// ---------------- zero deg ----------------
__global__ void zero_kernel() {
    int i = blockIdx.x * blockDim.x + threadIdx.x;
    if (i < NN) g_deg[i] = 0;
}

// ---------------- W1 fp32 -> fp16 (once per launch) ----------------
__global__ void w1cvt_kernel(const float* __restrict__ W1) {
    int i = blockIdx.x * blockDim.x + threadIdx.x;
    if (i < IN_DIM * IN_DIM / 2) {
        float2 f = ((const float2*)W1)[i];
        ((__half2*)g_W1h)[i] = __floats2half2_rn(f.x, f.y);
    }
}

// ---- GEMM1 on tensor cores: 128-row tile, 512 thr, fused el1/er1, fp16 out ----
__global__ __launch_bounds__(512) void gemm1_kernel(const float* __restrict__ h,
                                                    const float* __restrict__ al1,
                                                    const float* __restrict__ ar1) {
    extern __shared__ __half smh[];
    __half* As = smh;                          // [128][A_STRIDE]
    __half* Ws = smh + G1_ROWS * A_STRIDE;     // [128][A_STRIDE]
    int t = threadIdx.x;
    int row0 = blockIdx.x * G1_ROWS;

    for (int i = t; i < IN_DIM * IN_DIM / 8; i += 512) {
        int r = i >> 4, c8 = i & 15;
        uint4 v = ((const uint4*)g_W1h)[i];
        *(uint4*)(Ws + r * A_STRIDE + c8 * 8) = v;
    }
    const float4* H4 = (const float4*)h;
    for (int i = t; i < G1_ROWS * IN_DIM / 4; i += 512) {
        int r = i >> 5, c4 = i & 31;
        int g = row0 + r;
        float4 f = (g < NN) ? H4[g * 32 + c4] : make_float4(0.f, 0.f, 0.f, 0.f);
        uint2 v;
        v.x = f2_to_h2u(f.x, f.y);
        v.y = f2_to_h2u(f.z, f.w);
        *(uint2*)(As + r * A_STRIDE + c4 * 4) = v;
    }
    __syncthreads();

    int w = t >> 5, lane = t & 31;
    int rw = (w & 7) * 16;
    int ch = (w >> 3) * 64;

    uint a_base = (uint)__cvta_generic_to_shared(
        As + (rw + (lane & 15)) * A_STRIDE + ((lane >> 4) * 8));
    uint b_base = (uint)__cvta_generic_to_shared(
        Ws + (lane & 15) * A_STRIDE + ch + ((lane >> 4) * 8));

    float acc[8][4];
    #pragma unroll
    for (int j = 0; j < 8; ++j)
        #pragma unroll
        for (int c = 0; c < 4; ++c) acc[j][c] = 0.f;

    #pragma unroll
    for (int kb = 0; kb < 8; ++kb) {
        uint a0, a1, a2, a3;
        asm volatile("ldmatrix.sync.aligned.m8n8.x4.shared.b16 {%0,%1,%2,%3}, [%4];"
                     : "=r"(a0), "=r"(a1), "=r"(a2), "=r"(a3)
                     : "r"(a_base + kb * 32));
        #pragma unroll
        for (int p = 0; p < 4; ++p) {
            uint b0, b1, b2, b3;
            asm volatile("ldmatrix.sync.aligned.m8n8.x4.trans.shared.b16 {%0,%1,%2,%3}, [%4];"
                         : "=r"(b0), "=r"(b1), "=r"(b2), "=r"(b3)
                         : "r"(b_base + kb * 16 * A_STRIDE * 2 + p * 32));
            asm volatile("mma.sync.aligned.m16n8k16.row.col.f32.f16.f16.f32 "
                         "{%0,%1,%2,%3}, {%4,%5,%6,%7}, {%8,%9}, {%0,%1,%2,%3};"
                         : "+f"(acc[2*p][0]), "+f"(acc[2*p][1]), "+f"(acc[2*p][2]), "+f"(acc[2*p][3])
                         : "r"(a0), "r"(a1), "r"(a2), "r"(a3), "r"(b0), "r"(b1));
            asm volatile("mma.sync.aligned.m16n8k16.row.col.f32.f16.f16.f32 "
                         "{%0,%1,%2,%3}, {%4,%5,%6,%7}, {%8,%9}, {%0,%1,%2,%3};"
                         : "+f"(acc[2*p+1][0]), "+f"(acc[2*p+1][1]), "+f"(acc[2*p+1][2]), "+f"(acc[2*p+1][3])
                         : "r"(a0), "r"(a1), "r"(a2), "r"(a3), "r"(b2), "r"(b3));
        }
    }

    int g0 = lane >> 2, quad = lane & 3;
    int r0g = row0 + rw + g0;
    int r1g = r0g + 8;
    int h0 = (w >> 3) * 2;

    float pe[2][2] = {{0.f, 0.f}, {0.f, 0.f}};
    float pr[2][2] = {{0.f, 0.f}, {0.f, 0.f}};

    #pragma unroll
    for (int j = 0; j < 8; ++j) {
        int n0 = ch + j * 8 + quad * 2;
        float2 av = *(const float2*)(al1 + n0);
        float2 rv = *(const float2*)(ar1 + n0);
        if (r0g < NN) ((uint*)g_feat1h)[(r0g * IN_DIM + n0) >> 1] = f2_to_h2u(acc[j][0], acc[j][1]);
        if (r1g < NN) ((uint*)g_feat1h)[(r1g * IN_DIM + n0) >> 1] = f2_to_h2u(acc[j][2], acc[j][3]);
        int hi = j >> 2;
        pe[hi][0] += acc[j][0] * av.x + acc[j][1] * av.y;
        pe[hi][1] += acc[j][2] * av.x + acc[j][3] * av.y;
        pr[hi][0] += acc[j][0] * rv.x + acc[j][1] * rv.y;
        pr[hi][1] += acc[j][2] * rv.x + acc[j][3] * rv.y;
    }
    #pragma unroll
    for (int hi = 0; hi < 2; ++hi)
        #pragma unroll
        for (int rr = 0; rr < 2; ++rr) {
            float e = pe[hi][rr], r = pr[hi][rr];
            e += __shfl_xor_sync(0xFFFFFFFFu, e, 1);
            e += __shfl_xor_sync(0xFFFFFFFFu, e, 2);
            r += __shfl_xor_sync(0xFFFFFFFFu, r, 1);
            r += __shfl_xor_sync(0xFFFFFFFFu, r, 2);
            int g = rr ? r1g : r0g;
            if (quad == 0 && g < NN) {
                g_el1[g * 4 + h0 + hi] = e;
                g_er1[g * 4 + h0 + hi] = r;
            }
        }
}

// ---------------- CSR build ----------------
__global__ void hist_kernel(const int* __restrict__ dst) {
    int i = blockIdx.x * blockDim.x + threadIdx.x;
    if (i < EE) g_rank[i] = atomicAdd(&g_deg[dst[i]], 1);
}

__global__ void scan1_kernel() {
    __shared__ int ws[32];
    int t = threadIdx.x;
    int lane = t & 31, wp = t >> 5;
    int i = blockIdx.x * SCAN_B + t;
    int v = (i < NN) ? g_deg[i] : 0;
    int x = v;
    #pragma unroll
    for (int off = 1; off < 32; off <<= 1) {
        int y = __shfl_up_sync(0xFFFFFFFFu, x, off);
        if (lane >= off) x += y;
    }
    if (lane == 31) ws[wp] = x;
    __syncthreads();
    if (wp == 0) {
        int o = ws[lane];
        int s = o;
        #pragma unroll
        for (int off = 1; off < 32; off <<= 1) {
            int y = __shfl_up_sync(0xFFFFFFFFu, s, off);
            if (lane >= off) s += y;
        }
        ws[lane] = s - o;
    }
    __syncthreads();
    int base = ws[wp];
    if (i < NN) g_rowptr[i] = x - v + base;
    if (t == SCAN_B - 1) g_bsum[blockIdx.x] = x + base;
}

__global__ void scan2_kernel() {
    int t = threadIdx.x;
    int lane = t & 31, wp = t >> 5;
    int v = (t < NB) ? g_bsum[t] : 0;
    int x = v;
    #pragma unroll
    for (int off = 1; off < 32; off <<= 1) {
        int y = __shfl_up_sync(0xFFFFFFFFu, x, off);
        if (lane >= off) x += y;
    }
    __shared__ int wsum[4];
    if (lane == 31) wsum[wp] = x;
    __syncthreads();
    int add = 0;
    for (int w = 0; w < wp; ++w) add += wsum[w];
    if (t < NB) g_boff[t] = x - v + add;
}

__global__ void scan3_kernel() {
    int i = blockIdx.x * SCAN_B + threadIdx.x;
    if (i < NN) g_rowptr[i] += g_boff[blockIdx.x];
    if (i == 0) g_rowptr[NN] = EE;
}

__global__ void scatter_kernel(const int* __restrict__ src, const int* __restrict__ dst) {
    int i = blockIdx.x * blockDim.x + threadIdx.x;
    if (i < EE) {
        int d = dst[i];
        int pos = g_rowptr[d] + g_rank[i];
        g_esrc[pos] = src[i];
        g_edst[pos] = d;
    }
}

// ---- per-edge softmax weights, layer 1 (edge-parallel, coalesced) ----
__global__ void ew1_kernel() {
    int i = blockIdx.x * blockDim.x + threadIdx.x;
    if (i >= EE) return;
    int s = g_esrc[i], d = g_edst[i];
    float4 el = ((const float4*)g_el1)[s];
    float4 er = ((const float4*)g_er1)[d];
    float4 w;
    float e;
    e = el.x + er.x; e = fmaxf(e, NEG_SLOPE * e); w.x = __expf(e);
    e = el.y + er.y; e = fmaxf(e, NEG_SLOPE * e); w.y = __expf(e);
    e = el.z + er.z; e = fmaxf(e, NEG_SLOPE * e); w.z = __expf(e);
    e = el.w + er.w; e = fmaxf(e, NEG_SLOPE * e); w.w = __expf(e);
    ((float4*)g_ew1)[i] = w;
}

// ---- per-edge softmax weights, layer 2 ----
__global__ void ew2_kernel() {
    int i = blockIdx.x * blockDim.x + threadIdx.x;
    if (i >= EE) return;
    int s = g_esrc[i], d = g_edst[i];
    float e = g_el2[s] + g_er2[d];
    e = fmaxf(e, NEG_SLOPE * e);
    g_ew2[i] = __expf(e);
}

// ------- layer-1 aggregation: warp/node, 4-edge unroll, precomputed w -------
__global__ __launch_bounds__(256) void agg1_kernel(const float* __restrict__ b1) {
    int n = (blockIdx.x * blockDim.x + threadIdx.x) >> 5;
    int l = threadIdx.x & 31;
    if (n >= NN) return;
    int hh = l >> 3;
    int s0 = g_rowptr[n], s1 = g_rowptr[n + 1];

    const uint2* f2 = (const uint2*)g_feat1h;
    ull aA0 = 0, aA1 = 0, aB0 = 0, aB1 = 0;
    float dsA = 0.f, dsB = 0.f;

    int i = s0;
    for (; i + 4 <= s1; i += 4) {
        int sa = g_esrc[i];
        int sb = g_esrc[i + 1];
        int sc = g_esrc[i + 2];
        int sd = g_esrc[i + 3];
        float wa = g_ew1[(i + 0) * 4 + hh];
        float wb = g_ew1[(i + 1) * 4 + hh];
        float wc = g_ew1[(i + 2) * 4 + hh];
        float wd = g_ew1[(i + 3) * 4 + hh];
        uint2 fa = f2[sa * 32 + l];
        uint2 fb = f2[sb * 32 + l];
        uint2 fc = f2[sc * 32 + l];
        uint2 fd = f2[sd * 32 + l];
        float2 fa0 = h2u_to_f2(fa.x), fa1 = h2u_to_f2(fa.y);
        float2 fb0 = h2u_to_f2(fb.x), fb1 = h2u_to_f2(fb.y);
        float2 fc0 = h2u_to_f2(fc.x), fc1 = h2u_to_f2(fc.y);
        float2 fd0 = h2u_to_f2(fd.x), fd1 = h2u_to_f2(fd.y);
        ull wa2 = pack2(wa, wa), wb2 = pack2(wb, wb);
        ull wc2 = pack2(wc, wc), wd2 = pack2(wd, wd);
        ffma2(aA0, wa2, pack2(fa0.x, fa0.y)); ffma2(aA1, wa2, pack2(fa1.x, fa1.y));
        ffma2(aB0, wb2, pack2(fb0.x, fb0.y)); ffma2(aB1, wb2, pack2(fb1.x, fb1.y));
        ffma2(aA0, wc2, pack2(fc0.x, fc0.y)); ffma2(aA1, wc2, pack2(fc1.x, fc1.y));
        ffma2(aB0, wd2, pack2(fd0.x, fd0.y)); ffma2(aB1, wd2, pack2(fd1.x, fd1.y));
        dsA += wa + wc; dsB += wb + wd;
    }
    for (; i < s1; ++i) {
        int sa = g_esrc[i];
        float wa = g_ew1[i * 4 + hh];
        uint2 fa = f2[sa * 32 + l];
        float2 fa0 = h2u_to_f2(fa.x), fa1 = h2u_to_f2(fa.y);
        ull wa2 = pack2(wa, wa);
        ffma2(aA0, wa2, pack2(fa0.x, fa0.y));
        ffma2(aA1, wa2, pack2(fa1.x, fa1.y));
        dsA += wa;
    }

    float inv = 1.0f / fmaxf(dsA + dsB, 1e-9f);
    float xA, yA, xB, yB, zA, wA, zB, wB;
    unpack2(aA0, xA, yA); unpack2(aB0, xB, yB);
    unpack2(aA1, zA, wA); unpack2(aB1, zB, wB);
    float4 bb = ((const float4*)b1)[l];
    float o0 = fmaxf((xA + xB) * inv + bb.x, 0.f);
    float o1 = fmaxf((yA + yB) * inv + bb.y, 0.f);
    float o2 = fmaxf((zA + zB) * inv + bb.z, 0.f);
    float o3 = fmaxf((wA + wB) * inv + bb.w, 0.f);
    uint2 v;
    v.x = f2_to_h2u(o0, o1);
    v.y = f2_to_h2u(o2, o3);
    ((uint2*)g_h1h)[n * 32 + l] = v;
}

// ------- GEMM2 on tensor cores: 128-row tile, fused el2/er2, fp16 out -------
__global__ __launch_bounds__(256) void gemm2_kernel(const float* __restrict__ W2,
                                                    const float* __restrict__ al2,
                                                    const float* __restrict__ ar2) {
    extern __shared__ __half smh[];
    __half* As = smh;
    __half* Bs = smh + G2_ROWS * A_STRIDE;
    int t = threadIdx.x;
    int row0 = blockIdx.x * G2_ROWS;

    for (int i = t; i < G2_ROWS * IN_DIM / 8; i += 256) {
        int r = i >> 4, c8 = i & 15;
        int g = row0 + r;
        uint4 v = (g < NN) ? ((const uint4*)g_h1h)[g * 16 + c8]
                           : make_uint4(0u, 0u, 0u, 0u);
        *(uint4*)(As + r * A_STRIDE + c8 * 8) = v;
    }
    for (int i = t; i < IN_DIM * OUT_DIM; i += 256) {
        int r = i / OUT_DIM, c = i - r * OUT_DIM;
        Bs[r * B2_STRIDE + c] = __float2half_rn(W2[i]);
    }
    for (int i = t; i < IN_DIM * 8; i += 256) {
        int r = i >> 3, c = i & 7;
        Bs[r * B2_STRIDE + OUT_DIM + c] = __float2half_rn(0.f);
    }
    __syncthreads();

    int w = t >> 5, lane = t & 31;
    int rw = w * 16;

    uint a_base = (uint)__cvta_generic_to_shared(
        As + (rw + (lane & 15)) * A_STRIDE + ((lane >> 4) * 8));
    uint b_base = (uint)__cvta_generic_to_shared(
        Bs + (lane & 15) * B2_STRIDE + ((lane >> 4) * 8));

    float acc[6][4];
    #pragma unroll
    for (int j = 0; j < 6; ++j)
        #pragma unroll
        for (int c = 0; c < 4; ++c) acc[j][c] = 0.f;

    #pragma unroll
    for (int kb = 0; kb < 8; ++kb) {
        uint a0, a1, a2, a3;
        asm volatile("ldmatrix.sync.aligned.m8n8.x4.shared.b16 {%0,%1,%2,%3}, [%4];"
                     : "=r"(a0), "=r"(a1), "=r"(a2), "=r"(a3)
                     : "r"(a_base + kb * 32));
        #pragma unroll
        for (int p = 0; p < 3; ++p) {
            uint b0, b1, b2, b3;
            asm volatile("ldmatrix.sync.aligned.m8n8.x4.trans.shared.b16 {%0,%1,%2,%3}, [%4];"
                         : "=r"(b0), "=r"(b1), "=r"(b2), "=r"(b3)
                         : "r"(b_base + kb * 16 * B2_STRIDE * 2 + p * 32));
            asm volatile("mma.sync.aligned.m16n8k16.row.col.f32.f16.f16.f32 "
                         "{%0,%1,%2,%3}, {%4,%5,%6,%7}, {%8,%9}, {%0,%1,%2,%3};"
                         : "+f"(acc[2*p][0]), "+f"(acc[2*p][1]), "+f"(acc[2*p][2]), "+f"(acc[2*p][3])
                         : "r"(a0), "r"(a1), "r"(a2), "r"(a3), "r"(b0), "r"(b1));
            asm volatile("mma.sync.aligned.m16n8k16.row.col.f32.f16.f16.f32 "
                         "{%0,%1,%2,%3}, {%4,%5,%6,%7}, {%8,%9}, {%0,%1,%2,%3};"
                         : "+f"(acc[2*p+1][0]), "+f"(acc[2*p+1][1]), "+f"(acc[2*p+1][2]), "+f"(acc[2*p+1][3])
                         : "r"(a0), "r"(a1), "r"(a2), "r"(a3), "r"(b2), "r"(b3));
        }
    }

    int g0 = lane >> 2, quad = lane & 3;
    int r0g = row0 + rw + g0;
    int r1g = r0g + 8;

    float p0 = 0.f, p1 = 0.f, q0 = 0.f, q1 = 0.f;
    #pragma unroll
    for (int j = 0; j < 5; ++j) {
        int n0 = j * 8 + quad * 2;
        float2 av = *(const float2*)(al2 + n0);
        float2 rv = *(const float2*)(ar2 + n0);
        if (r0g < NN) ((uint*)g_feat2h)[(r0g * OUT_DIM + n0) >> 1] = f2_to_h2u(acc[j][0], acc[j][1]);
        if (r1g < NN) ((uint*)g_feat2h)[(r1g * OUT_DIM + n0) >> 1] = f2_to_h2u(acc[j][2], acc[j][3]);
        p0 += acc[j][0] * av.x + acc[j][1] * av.y;
        p1 += acc[j][2] * av.x + acc[j][3] * av.y;
        q0 += acc[j][0] * rv.x + acc[j][1] * rv.y;
        q1 += acc[j][2] * rv.x + acc[j][3] * rv.y;
    }
    #pragma unroll
    for (int off = 1; off <= 2; off <<= 1) {
        p0 += __shfl_xor_sync(0xFFFFFFFFu, p0, off);
        p1 += __shfl_xor_sync(0xFFFFFFFFu, p1, off);
        q0 += __shfl_xor_sync(0xFFFFFFFFu, q0, off);
        q1 += __shfl_xor_sync(0xFFFFFFFFu, q1, off);
    }
    if (quad == 0) {
        if (r0g < NN) { g_el2[r0g] = p0; g_er2[r0g] = q0; }
        if (r1g < NN) { g_el2[r1g] = p1; g_er2[r1g] = q1; }
    }
}

// ------- layer-2 aggregation: warp/node, 4-edge unroll, precomputed w -------
__global__ __launch_bounds__(256) void agg2_kernel(const float* __restrict__ b2, float* __restrict__ out) {
    int n = (blockIdx.x * blockDim.x + threadIdx.x) >> 5;
    int l = threadIdx.x & 31;
    if (n >= NN) return;
    int s0 = g_rowptr[n], s1 = g_rowptr[n + 1];
    int lc = (l < 20) ? l : 19;

    const uint* f2 = (const uint*)g_feat2h;
    ull aA = 0, aB = 0;
    float dsA = 0.f, dsB = 0.f;

    int i = s0;
    for (; i + 4 <= s1; i += 4) {
        int sa = g_esrc[i];
        int sb = g_esrc[i + 1];
        int sc = g_esrc[i + 2];
        int sd = g_esrc[i + 3];
        float wa = g_ew2[i];
        float wb = g_ew2[i + 1];
        float wc = g_ew2[i + 2];
        float wd = g_ew2[i + 3];
        uint fa = f2[sa * 20 + lc];
        uint fb = f2[sb * 20 + lc];
        uint fc = f2[sc * 20 + lc];
        uint fd = f2[sd * 20 + lc];
        float2 fav = h2u_to_f2(fa), fbv = h2u_to_f2(fb);
        float2 fcv = h2u_to_f2(fc), fdv = h2u_to_f2(fd);
        ffma2(aA, pack2(wa, wa), pack2(fav.x, fav.y));
        ffma2(aB, pack2(wb, wb), pack2(fbv.x, fbv.y));
        ffma2(aA, pack2(wc, wc), pack2(fcv.x, fcv.y));
        ffma2(aB, pack2(wd, wd), pack2(fdv.x, fdv.y));
        dsA += wa + wc; dsB += wb + wd;
    }
    for (; i < s1; ++i) {
        int sa = g_esrc[i];
        float wa = g_ew2[i];
        float2 fav = h2u_to_f2(f2[sa * 20 + lc]);
        ffma2(aA, pack2(wa, wa), pack2(fav.x, fav.y));
        dsA += wa;
    }

    if (l < 20) {
        float inv = 1.0f / fmaxf(dsA + dsB, 1e-9f);
        float xa, ya, xb, yb;
        unpack2(aA, xa, ya); unpack2(aB, xb, yb);
        float o0 = (xa + xb) * inv + b2[2 * l];
        float o1 = (ya + yb) * inv + b2[2 * l + 1];
        ((ull*)out)[n * 20 + l] = pack2(o0, o1);
    }
}

// ---------------- side stream for CSR/GEMM1 overlap ----------------
namespace {
struct Aux {
    cudaStream_t s2;
    cudaEvent_t fork, join;
    bool ok;
    Aux() : s2(nullptr), fork(nullptr), join(nullptr), ok(false) {
        if (cudaStreamCreateWithFlags(&s2, cudaStreamNonBlocking) != cudaSuccess) return;
        if (cudaEventCreateWithFlags(&fork, cudaEventDisableTiming) != cudaSuccess) return;
        if (cudaEventCreateWithFlags(&join, cudaEventDisableTiming) != cudaSuccess) return;
        ok = true;
    }
};
Aux g_aux;
}

// ---------------- launch ----------------
extern "C" void kernel_launch(void* const* d_in, const int* in_sizes, int n_in,
                              void* d_out, int out_size) {
    const float* h   = (const float*)d_in[0];
    const int*   src = (const int*)  d_in[1];
    const int*   dst = (const int*)  d_in[2];
    const float* W1  = (const float*)d_in[3];
    const float* al1 = (const float*)d_in[4];
    const float* ar1 = (const float*)d_in[5];
    const float* b1  = (const float*)d_in[6];
    const float* W2  = (const float*)d_in[7];
    const float* al2 = (const float*)d_in[8];
    const float* ar2 = (const float*)d_in[9];
    const float* b2  = (const float*)d_in[10];
    float* out = (float*)d_out;

    cudaFuncSetAttribute(gemm1_kernel, cudaFuncAttributeMaxDynamicSharedMemorySize, G1_SMEM);
    cudaFuncSetAttribute(gemm2_kernel, cudaFuncAttributeMaxDynamicSharedMemorySize, G2_SMEM);

    int nwarp_blocks = (NN * 32 + 255) / 256;
    int eblocks = (EE + 255) / 256;
    int g1blocks = (NN + G1_ROWS - 1) / G1_ROWS;
    int g2blocks = (NN + G2_ROWS - 1) / G2_ROWS;

    if (g_aux.ok) {
        cudaEventRecord(g_aux.fork, 0);
        cudaStreamWaitEvent(g_aux.s2, g_aux.fork, 0);
        zero_kernel<<<(NN + 255) / 256, 256, 0, g_aux.s2>>>();            // 1
        hist_kernel<<<eblocks, 256, 0, g_aux.s2>>>(dst);                  // 2
        w1cvt_kernel<<<(IN_DIM * IN_DIM / 2 + 255) / 256, 256>>>(W1);     // 3 (main)
        gemm1_kernel<<<g1blocks, 512, G1_SMEM>>>(h, al1, ar1);            // 4 (main, profiled)
        scan1_kernel<<<NB, SCAN_B, 0, g_aux.s2>>>();                      // 5
        scan2_kernel<<<1, 128, 0, g_aux.s2>>>();                          // 6
        scan3_kernel<<<NB, SCAN_B, 0, g_aux.s2>>>();                      // 7
        scatter_kernel<<<eblocks, 256, 0, g_aux.s2>>>(src, dst);          // 8
        cudaEventRecord(g_aux.join, g_aux.s2);
        cudaStreamWaitEvent(0, g_aux.join, 0);
    } else {
        zero_kernel<<<(NN + 255) / 256, 256>>>();
        hist_kernel<<<eblocks, 256>>>(dst);
        w1cvt_kernel<<<(IN_DIM * IN_DIM / 2 + 255) / 256, 256>>>(W1);
        gemm1_kernel<<<g1blocks, 512, G1_SMEM>>>(h, al1, ar1);
        scan1_kernel<<<NB, SCAN_B>>>();
        scan2_kernel<<<1, 128>>>();
        scan3_kernel<<<NB, SCAN_B>>>();
        scatter_kernel<<<eblocks, 256>>>(src, dst);
    }

    ew1_kernel<<<eblocks, 256>>>();
    agg1_kernel<<<nwarp_blocks, 256>>>(b1);
    gemm2_kernel<<<g2blocks, 256, G2_SMEM>>>(W2, al2, ar2);
    ew2_kernel<<<eblocks, 256>>>();
    agg2_kernel<<<nwarp_blocks, 256>>>(b2, out);
}

// round 16
// speedup vs baseline: 1.1715x; 1.0019x over previous
#include <cuda_runtime.h>
#include <cuda_fp16.h>
#include <string.h>

#define NN 100000
#define EE 1600000
#define IN_DIM 128
#define HID 32
#define HEADS 4
#define OUT_DIM 40
#define NEG_SLOPE 0.2f

#define G1_ROWS 128
#define A_STRIDE 136
#define G1_SMEM ((G1_ROWS*A_STRIDE + IN_DIM*A_STRIDE) * 2)   // 69632 B
#define G2_ROWS 128
#define B2_STRIDE 48
#define G2_SMEM ((G2_ROWS*A_STRIDE + IN_DIM*B2_STRIDE) * 2)  // 47104 B
#define SCAN_B 1024
#define NB ((NN + SCAN_B - 1) / SCAN_B)   // 98

typedef unsigned long long ull;
typedef unsigned int uint;

// ---------------- f32x2 packed-math helpers (sm_103a) ----------------
__device__ __forceinline__ ull pack2(float a, float b) {
    ull r; asm("mov.b64 %0,{%1,%2};" : "=l"(r) : "f"(a), "f"(b)); return r;
}
__device__ __forceinline__ void unpack2(ull p, float& a, float& b) {
    asm("mov.b64 {%0,%1},%2;" : "=f"(a), "=f"(b) : "l"(p));
}
__device__ __forceinline__ void ffma2(ull& acc, ull a, ull b) {
    asm("fma.rn.f32x2 %0,%1,%2,%0;" : "+l"(acc) : "l"(a), "l"(b));
}
// ---------------- fp16 bit-cast helpers ----------------
__device__ __forceinline__ uint f2_to_h2u(float a, float b) {
    __half2 h = __floats2half2_rn(a, b);
    uint u; memcpy(&u, &h, 4); return u;
}
__device__ __forceinline__ float2 h2u_to_f2(uint u) {
    __half2 h; memcpy(&h, &u, 4);
    return __half22float2(h);
}

// ---------------- scratch (device globals: allocation-free) ----------------
__device__ __half g_feat1h[NN * IN_DIM];
__device__ float  g_el1[NN * HEADS];
__device__ float  g_er1[NN * HEADS];
__device__ __half g_h1h[NN * IN_DIM];
__device__ __half g_feat2h[NN * OUT_DIM];
__device__ float  g_el2[NN];
__device__ float  g_er2[NN];
__device__ __half g_W1h[IN_DIM * IN_DIM];
__device__ float  g_ew1[EE * HEADS];       // per-edge per-head softmax weights (layer 1)
__device__ float  g_ew2[EE];               // per-edge weights (layer 2)
__device__ int    g_deg[NN];
__device__ int    g_rank[EE];
__device__ int    g_rowptr[NN + 1];
__device__ int    g_esrc[EE];
__device__ int    g_edst[EE];
__device__ int    g_bsum[128];
__device__ int    g_boff[128];

// ---------------- zero deg ----------------
__global__ void zero_kernel() {
    int i = blockIdx.x * blockDim.x + threadIdx.x;
    if (i < NN) g_deg[i] = 0;
}

// ---------------- W1 fp32 -> fp16 (once per launch) ----------------
__global__ void w1cvt_kernel(const float* __restrict__ W1) {
    int i = blockIdx.x * blockDim.x + threadIdx.x;
    if (i < IN_DIM * IN_DIM / 2) {
        float2 f = ((const float2*)W1)[i];
        ((__half2*)g_W1h)[i] = __floats2half2_rn(f.x, f.y);
    }
}

// ---- GEMM1 on tensor cores: 128-row tile, 512 thr, fused el1/er1, fp16 out ----
__global__ __launch_bounds__(512) void gemm1_kernel(const float* __restrict__ h,
                                                    const float* __restrict__ al1,
                                                    const float* __restrict__ ar1) {
    extern __shared__ __half smh[];
    __half* As = smh;                          // [128][A_STRIDE]
    __half* Ws = smh + G1_ROWS * A_STRIDE;     // [128][A_STRIDE]
    int t = threadIdx.x;
    int row0 = blockIdx.x * G1_ROWS;

    for (int i = t; i < IN_DIM * IN_DIM / 8; i += 512) {
        int r = i >> 4, c8 = i & 15;
        uint4 v = ((const uint4*)g_W1h)[i];
        *(uint4*)(Ws + r * A_STRIDE + c8 * 8) = v;
    }
    const float4* H4 = (const float4*)h;
    for (int i = t; i < G1_ROWS * IN_DIM / 4; i += 512) {
        int r = i >> 5, c4 = i & 31;
        int g = row0 + r;
        float4 f = (g < NN) ? H4[g * 32 + c4] : make_float4(0.f, 0.f, 0.f, 0.f);
        uint2 v;
        v.x = f2_to_h2u(f.x, f.y);
        v.y = f2_to_h2u(f.z, f.w);
        *(uint2*)(As + r * A_STRIDE + c4 * 4) = v;
    }
    __syncthreads();

    int w = t >> 5, lane = t & 31;
    int rw = (w & 7) * 16;
    int ch = (w >> 3) * 64;

    uint a_base = (uint)__cvta_generic_to_shared(
        As + (rw + (lane & 15)) * A_STRIDE + ((lane >> 4) * 8));
    uint b_base = (uint)__cvta_generic_to_shared(
        Ws + (lane & 15) * A_STRIDE + ch + ((lane >> 4) * 8));

    float acc[8][4];
    #pragma unroll
    for (int j = 0; j < 8; ++j)
        #pragma unroll
        for (int c = 0; c < 4; ++c) acc[j][c] = 0.f;

    #pragma unroll
    for (int kb = 0; kb < 8; ++kb) {
        uint a0, a1, a2, a3;
        asm volatile("ldmatrix.sync.aligned.m8n8.x4.shared.b16 {%0,%1,%2,%3}, [%4];"
                     : "=r"(a0), "=r"(a1), "=r"(a2), "=r"(a3)
                     : "r"(a_base + kb * 32));
        #pragma unroll
        for (int p = 0; p < 4; ++p) {
            uint b0, b1, b2, b3;
            asm volatile("ldmatrix.sync.aligned.m8n8.x4.trans.shared.b16 {%0,%1,%2,%3}, [%4];"
                         : "=r"(b0), "=r"(b1), "=r"(b2), "=r"(b3)
                         : "r"(b_base + kb * 16 * A_STRIDE * 2 + p * 32));
            asm volatile("mma.sync.aligned.m16n8k16.row.col.f32.f16.f16.f32 "
                         "{%0,%1,%2,%3}, {%4,%5,%6,%7}, {%8,%9}, {%0,%1,%2,%3};"
                         : "+f"(acc[2*p][0]), "+f"(acc[2*p][1]), "+f"(acc[2*p][2]), "+f"(acc[2*p][3])
                         : "r"(a0), "r"(a1), "r"(a2), "r"(a3), "r"(b0), "r"(b1));
            asm volatile("mma.sync.aligned.m16n8k16.row.col.f32.f16.f16.f32 "
                         "{%0,%1,%2,%3}, {%4,%5,%6,%7}, {%8,%9}, {%0,%1,%2,%3};"
                         : "+f"(acc[2*p+1][0]), "+f"(acc[2*p+1][1]), "+f"(acc[2*p+1][2]), "+f"(acc[2*p+1][3])
                         : "r"(a0), "r"(a1), "r"(a2), "r"(a3), "r"(b2), "r"(b3));
        }
    }

    int g0 = lane >> 2, quad = lane & 3;
    int r0g = row0 + rw + g0;
    int r1g = r0g + 8;
    int h0 = (w >> 3) * 2;

    float pe[2][2] = {{0.f, 0.f}, {0.f, 0.f}};
    float pr[2][2] = {{0.f, 0.f}, {0.f, 0.f}};

    #pragma unroll
    for (int j = 0; j < 8; ++j) {
        int n0 = ch + j * 8 + quad * 2;
        float2 av = *(const float2*)(al1 + n0);
        float2 rv = *(const float2*)(ar1 + n0);
        if (r0g < NN) ((uint*)g_feat1h)[(r0g * IN_DIM + n0) >> 1] = f2_to_h2u(acc[j][0], acc[j][1]);
        if (r1g < NN) ((uint*)g_feat1h)[(r1g * IN_DIM + n0) >> 1] = f2_to_h2u(acc[j][2], acc[j][3]);
        int hi = j >> 2;
        pe[hi][0] += acc[j][0] * av.x + acc[j][1] * av.y;
        pe[hi][1] += acc[j][2] * av.x + acc[j][3] * av.y;
        pr[hi][0] += acc[j][0] * rv.x + acc[j][1] * rv.y;
        pr[hi][1] += acc[j][2] * rv.x + acc[j][3] * rv.y;
    }
    #pragma unroll
    for (int hi = 0; hi < 2; ++hi)
        #pragma unroll
        for (int rr = 0; rr < 2; ++rr) {
            float e = pe[hi][rr], r = pr[hi][rr];
            e += __shfl_xor_sync(0xFFFFFFFFu, e, 1);
            e += __shfl_xor_sync(0xFFFFFFFFu, e, 2);
            r += __shfl_xor_sync(0xFFFFFFFFu, r, 1);
            r += __shfl_xor_sync(0xFFFFFFFFu, r, 2);
            int g = rr ? r1g : r0g;
            if (quad == 0 && g < NN) {
                g_el1[g * 4 + h0 + hi] = e;
                g_er1[g * 4 + h0 + hi] = r;
            }
        }
}

// ---------------- CSR build ----------------
__global__ void hist_kernel(const int* __restrict__ dst) {
    int i = blockIdx.x * blockDim.x + threadIdx.x;
    if (i < EE) g_rank[i] = atomicAdd(&g_deg[dst[i]], 1);
}

__global__ void scan1_kernel() {
    __shared__ int ws[32];
    int t = threadIdx.x;
    int lane = t & 31, wp = t >> 5;
    int i = blockIdx.x * SCAN_B + t;
    int v = (i < NN) ? g_deg[i] : 0;
    int x = v;
    #pragma unroll
    for (int off = 1; off < 32; off <<= 1) {
        int y = __shfl_up_sync(0xFFFFFFFFu, x, off);
        if (lane >= off) x += y;
    }
    if (lane == 31) ws[wp] = x;
    __syncthreads();
    if (wp == 0) {
        int o = ws[lane];
        int s = o;
        #pragma unroll
        for (int off = 1; off < 32; off <<= 1) {
            int y = __shfl_up_sync(0xFFFFFFFFu, s, off);
            if (lane >= off) s += y;
        }
        ws[lane] = s - o;
    }
    __syncthreads();
    int base = ws[wp];
    if (i < NN) g_rowptr[i] = x - v + base;
    if (t == SCAN_B - 1) g_bsum[blockIdx.x] = x + base;
}

__global__ void scan2_kernel() {
    int t = threadIdx.x;
    int lane = t & 31, wp = t >> 5;
    int v = (t < NB) ? g_bsum[t] : 0;
    int x = v;
    #pragma unroll
    for (int off = 1; off < 32; off <<= 1) {
        int y = __shfl_up_sync(0xFFFFFFFFu, x, off);
        if (lane >= off) x += y;
    }
    __shared__ int wsum[4];
    if (lane == 31) wsum[wp] = x;
    __syncthreads();
    int add = 0;
    for (int w = 0; w < wp; ++w) add += wsum[w];
    if (t < NB) g_boff[t] = x - v + add;
}

__global__ void scan3_kernel() {
    int i = blockIdx.x * SCAN_B + threadIdx.x;
    if (i < NN) g_rowptr[i] += g_boff[blockIdx.x];
    if (i == 0) g_rowptr[NN] = EE;
}

__global__ void scatter_kernel(const int* __restrict__ src, const int* __restrict__ dst) {
    int i = blockIdx.x * blockDim.x + threadIdx.x;
    if (i < EE) {
        int d = dst[i];
        int pos = g_rowptr[d] + g_rank[i];
        g_esrc[pos] = src[i];
        g_edst[pos] = d;
    }
}

// ---- per-edge softmax weights, layer 1 (edge-parallel, coalesced) ----
__global__ void ew1_kernel() {
    int i = blockIdx.x * blockDim.x + threadIdx.x;
    if (i >= EE) return;
    int s = g_esrc[i], d = g_edst[i];
    float4 el = ((const float4*)g_el1)[s];
    float4 er = ((const float4*)g_er1)[d];
    float4 w;
    float e;
    e = el.x + er.x; e = fmaxf(e, NEG_SLOPE * e); w.x = __expf(e);
    e = el.y + er.y; e = fmaxf(e, NEG_SLOPE * e); w.y = __expf(e);
    e = el.z + er.z; e = fmaxf(e, NEG_SLOPE * e); w.z = __expf(e);
    e = el.w + er.w; e = fmaxf(e, NEG_SLOPE * e); w.w = __expf(e);
    ((float4*)g_ew1)[i] = w;
}

// ---- per-edge softmax weights, layer 2 ----
__global__ void ew2_kernel() {
    int i = blockIdx.x * blockDim.x + threadIdx.x;
    if (i >= EE) return;
    int s = g_esrc[i], d = g_edst[i];
    float e = g_el2[s] + g_er2[d];
    e = fmaxf(e, NEG_SLOPE * e);
    g_ew2[i] = __expf(e);
}

// ------- layer-1 aggregation: warp/node, 8-edge unroll, precomputed w -------
__global__ __launch_bounds__(256) void agg1_kernel(const float* __restrict__ b1) {
    int n = (blockIdx.x * blockDim.x + threadIdx.x) >> 5;
    int l = threadIdx.x & 31;
    if (n >= NN) return;
    int hh = l >> 3;
    int s0 = g_rowptr[n], s1 = g_rowptr[n + 1];

    const uint2* f2 = (const uint2*)g_feat1h;
    ull aA0 = 0, aA1 = 0, aB0 = 0, aB1 = 0;
    float dsA = 0.f, dsB = 0.f;

    int i = s0;
    for (; i + 8 <= s1; i += 8) {
        int idx[8];
        float wv[8];
        uint2 ft[8];
        #pragma unroll
        for (int j = 0; j < 8; ++j) idx[j] = g_esrc[i + j];
        #pragma unroll
        for (int j = 0; j < 8; ++j) wv[j] = g_ew1[(i + j) * 4 + hh];
        #pragma unroll
        for (int j = 0; j < 8; ++j) ft[j] = f2[idx[j] * 32 + l];   // 8 gathers in flight
        #pragma unroll
        for (int j = 0; j < 8; ++j) {
            float2 f0 = h2u_to_f2(ft[j].x);
            float2 f1 = h2u_to_f2(ft[j].y);
            ull w2 = pack2(wv[j], wv[j]);
            if (j & 1) {
                ffma2(aB0, w2, pack2(f0.x, f0.y));
                ffma2(aB1, w2, pack2(f1.x, f1.y));
                dsB += wv[j];
            } else {
                ffma2(aA0, w2, pack2(f0.x, f0.y));
                ffma2(aA1, w2, pack2(f1.x, f1.y));
                dsA += wv[j];
            }
        }
    }
    for (; i < s1; ++i) {
        int sa = g_esrc[i];
        float wa = g_ew1[i * 4 + hh];
        uint2 fa = f2[sa * 32 + l];
        float2 fa0 = h2u_to_f2(fa.x), fa1 = h2u_to_f2(fa.y);
        ull wa2 = pack2(wa, wa);
        ffma2(aA0, wa2, pack2(fa0.x, fa0.y));
        ffma2(aA1, wa2, pack2(fa1.x, fa1.y));
        dsA += wa;
    }

    float inv = 1.0f / fmaxf(dsA + dsB, 1e-9f);
    float xA, yA, xB, yB, zA, wA, zB, wB;
    unpack2(aA0, xA, yA); unpack2(aB0, xB, yB);
    unpack2(aA1, zA, wA); unpack2(aB1, zB, wB);
    float4 bb = ((const float4*)b1)[l];
    float o0 = fmaxf((xA + xB) * inv + bb.x, 0.f);
    float o1 = fmaxf((yA + yB) * inv + bb.y, 0.f);
    float o2 = fmaxf((zA + zB) * inv + bb.z, 0.f);
    float o3 = fmaxf((wA + wB) * inv + bb.w, 0.f);
    uint2 v;
    v.x = f2_to_h2u(o0, o1);
    v.y = f2_to_h2u(o2, o3);
    ((uint2*)g_h1h)[n * 32 + l] = v;
}

// ------- GEMM2 on tensor cores: 128-row tile, fused el2/er2, fp16 out -------
__global__ __launch_bounds__(256) void gemm2_kernel(const float* __restrict__ W2,
                                                    const float* __restrict__ al2,
                                                    const float* __restrict__ ar2) {
    extern __shared__ __half smh[];
    __half* As = smh;
    __half* Bs = smh + G2_ROWS * A_STRIDE;
    int t = threadIdx.x;
    int row0 = blockIdx.x * G2_ROWS;

    for (int i = t; i < G2_ROWS * IN_DIM / 8; i += 256) {
        int r = i >> 4, c8 = i & 15;
        int g = row0 + r;
        uint4 v = (g < NN) ? ((const uint4*)g_h1h)[g * 16 + c8]
                           : make_uint4(0u, 0u, 0u, 0u);
        *(uint4*)(As + r * A_STRIDE + c8 * 8) = v;
    }
    for (int i = t; i < IN_DIM * OUT_DIM; i += 256) {
        int r = i / OUT_DIM, c = i - r * OUT_DIM;
        Bs[r * B2_STRIDE + c] = __float2half_rn(W2[i]);
    }
    for (int i = t; i < IN_DIM * 8; i += 256) {
        int r = i >> 3, c = i & 7;
        Bs[r * B2_STRIDE + OUT_DIM + c] = __float2half_rn(0.f);
    }
    __syncthreads();

    int w = t >> 5, lane = t & 31;
    int rw = w * 16;

    uint a_base = (uint)__cvta_generic_to_shared(
        As + (rw + (lane & 15)) * A_STRIDE + ((lane >> 4) * 8));
    uint b_base = (uint)__cvta_generic_to_shared(
        Bs + (lane & 15) * B2_STRIDE + ((lane >> 4) * 8));

    float acc[6][4];
    #pragma unroll
    for (int j = 0; j < 6; ++j)
        #pragma unroll
        for (int c = 0; c < 4; ++c) acc[j][c] = 0.f;

    #pragma unroll
    for (int kb = 0; kb < 8; ++kb) {
        uint a0, a1, a2, a3;
        asm volatile("ldmatrix.sync.aligned.m8n8.x4.shared.b16 {%0,%1,%2,%3}, [%4];"
                     : "=r"(a0), "=r"(a1), "=r"(a2), "=r"(a3)
                     : "r"(a_base + kb * 32));
        #pragma unroll
        for (int p = 0; p < 3; ++p) {
            uint b0, b1, b2, b3;
            asm volatile("ldmatrix.sync.aligned.m8n8.x4.trans.shared.b16 {%0,%1,%2,%3}, [%4];"
                         : "=r"(b0), "=r"(b1), "=r"(b2), "=r"(b3)
                         : "r"(b_base + kb * 16 * B2_STRIDE * 2 + p * 32));
            asm volatile("mma.sync.aligned.m16n8k16.row.col.f32.f16.f16.f32 "
                         "{%0,%1,%2,%3}, {%4,%5,%6,%7}, {%8,%9}, {%0,%1,%2,%3};"
                         : "+f"(acc[2*p][0]), "+f"(acc[2*p][1]), "+f"(acc[2*p][2]), "+f"(acc[2*p][3])
                         : "r"(a0), "r"(a1), "r"(a2), "r"(a3), "r"(b0), "r"(b1));
            asm volatile("mma.sync.aligned.m16n8k16.row.col.f32.f16.f16.f32 "
                         "{%0,%1,%2,%3}, {%4,%5,%6,%7}, {%8,%9}, {%0,%1,%2,%3};"
                         : "+f"(acc[2*p+1][0]), "+f"(acc[2*p+1][1]), "+f"(acc[2*p+1][2]), "+f"(acc[2*p+1][3])
                         : "r"(a0), "r"(a1), "r"(a2), "r"(a3), "r"(b2), "r"(b3));
        }
    }

    int g0 = lane >> 2, quad = lane & 3;
    int r0g = row0 + rw + g0;
    int r1g = r0g + 8;

    float p0 = 0.f, p1 = 0.f, q0 = 0.f, q1 = 0.f;
    #pragma unroll
    for (int j = 0; j < 5; ++j) {
        int n0 = j * 8 + quad * 2;
        float2 av = *(const float2*)(al2 + n0);
        float2 rv = *(const float2*)(ar2 + n0);
        if (r0g < NN) ((uint*)g_feat2h)[(r0g * OUT_DIM + n0) >> 1] = f2_to_h2u(acc[j][0], acc[j][1]);
        if (r1g < NN) ((uint*)g_feat2h)[(r1g * OUT_DIM + n0) >> 1] = f2_to_h2u(acc[j][2], acc[j][3]);
        p0 += acc[j][0] * av.x + acc[j][1] * av.y;
        p1 += acc[j][2] * av.x + acc[j][3] * av.y;
        q0 += acc[j][0] * rv.x + acc[j][1] * rv.y;
        q1 += acc[j][2] * rv.x + acc[j][3] * rv.y;
    }
    #pragma unroll
    for (int off = 1; off <= 2; off <<= 1) {
        p0 += __shfl_xor_sync(0xFFFFFFFFu, p0, off);
        p1 += __shfl_xor_sync(0xFFFFFFFFu, p1, off);
        q0 += __shfl_xor_sync(0xFFFFFFFFu, q0, off);
        q1 += __shfl_xor_sync(0xFFFFFFFFu, q1, off);
    }
    if (quad == 0) {
        if (r0g < NN) { g_el2[r0g] = p0; g_er2[r0g] = q0; }
        if (r1g < NN) { g_el2[r1g] = p1; g_er2[r1g] = q1; }
    }
}

// ------- layer-2 aggregation: warp/node, 8-edge unroll, precomputed w -------
__global__ __launch_bounds__(256) void agg2_kernel(const float* __restrict__ b2, float* __restrict__ out) {
    int n = (blockIdx.x * blockDim.x + threadIdx.x) >> 5;
    int l = threadIdx.x & 31;
    if (n >= NN) return;
    int s0 = g_rowptr[n], s1 = g_rowptr[n + 1];
    int lc = (l < 20) ? l : 19;

    const uint* f2 = (const uint*)g_feat2h;
    ull aA = 0, aB = 0;
    float dsA = 0.f, dsB = 0.f;

    int i = s0;
    for (; i + 8 <= s1; i += 8) {
        int idx[8];
        float wv[8];
        uint ft[8];
        #pragma unroll
        for (int j = 0; j < 8; ++j) idx[j] = g_esrc[i + j];
        #pragma unroll
        for (int j = 0; j < 8; ++j) wv[j] = g_ew2[i + j];
        #pragma unroll
        for (int j = 0; j < 8; ++j) ft[j] = f2[idx[j] * 20 + lc];
        #pragma unroll
        for (int j = 0; j < 8; ++j) {
            float2 fv = h2u_to_f2(ft[j]);
            ull w2 = pack2(wv[j], wv[j]);
            if (j & 1) { ffma2(aB, w2, pack2(fv.x, fv.y)); dsB += wv[j]; }
            else       { ffma2(aA, w2, pack2(fv.x, fv.y)); dsA += wv[j]; }
        }
    }
    for (; i < s1; ++i) {
        int sa = g_esrc[i];
        float wa = g_ew2[i];
        float2 fav = h2u_to_f2(f2[sa * 20 + lc]);
        ffma2(aA, pack2(wa, wa), pack2(fav.x, fav.y));
        dsA += wa;
    }

    if (l < 20) {
        float inv = 1.0f / fmaxf(dsA + dsB, 1e-9f);
        float xa, ya, xb, yb;
        unpack2(aA, xa, ya); unpack2(aB, xb, yb);
        float o0 = (xa + xb) * inv + b2[2 * l];
        float o1 = (ya + yb) * inv + b2[2 * l + 1];
        ((ull*)out)[n * 20 + l] = pack2(o0, o1);
    }
}

// ---------------- side stream for CSR/GEMM1 overlap ----------------
namespace {
struct Aux {
    cudaStream_t s2;
    cudaEvent_t fork, join;
    bool ok;
    Aux() : s2(nullptr), fork(nullptr), join(nullptr), ok(false) {
        if (cudaStreamCreateWithFlags(&s2, cudaStreamNonBlocking) != cudaSuccess) return;
        if (cudaEventCreateWithFlags(&fork, cudaEventDisableTiming) != cudaSuccess) return;
        if (cudaEventCreateWithFlags(&join, cudaEventDisableTiming) != cudaSuccess) return;
        ok = true;
    }
};
Aux g_aux;
}

// ---------------- launch ----------------
extern "C" void kernel_launch(void* const* d_in, const int* in_sizes, int n_in,
                              void* d_out, int out_size) {
    const float* h   = (const float*)d_in[0];
    const int*   src = (const int*)  d_in[1];
    const int*   dst = (const int*)  d_in[2];
    const float* W1  = (const float*)d_in[3];
    const float* al1 = (const float*)d_in[4];
    const float* ar1 = (const float*)d_in[5];
    const float* b1  = (const float*)d_in[6];
    const float* W2  = (const float*)d_in[7];
    const float* al2 = (const float*)d_in[8];
    const float* ar2 = (const float*)d_in[9];
    const float* b2  = (const float*)d_in[10];
    float* out = (float*)d_out;

    cudaFuncSetAttribute(gemm1_kernel, cudaFuncAttributeMaxDynamicSharedMemorySize, G1_SMEM);
    cudaFuncSetAttribute(gemm2_kernel, cudaFuncAttributeMaxDynamicSharedMemorySize, G2_SMEM);

    int nwarp_blocks = (NN * 32 + 255) / 256;
    int eblocks = (EE + 255) / 256;
    int g1blocks = (NN + G1_ROWS - 1) / G1_ROWS;
    int g2blocks = (NN + G2_ROWS - 1) / G2_ROWS;

    if (g_aux.ok) {
        cudaEventRecord(g_aux.fork, 0);
        cudaStreamWaitEvent(g_aux.s2, g_aux.fork, 0);
        zero_kernel<<<(NN + 255) / 256, 256, 0, g_aux.s2>>>();            // 1
        hist_kernel<<<eblocks, 256, 0, g_aux.s2>>>(dst);                  // 2
        w1cvt_kernel<<<(IN_DIM * IN_DIM / 2 + 255) / 256, 256>>>(W1);     // 3 (main)
        gemm1_kernel<<<g1blocks, 512, G1_SMEM>>>(h, al1, ar1);            // 4 (main, profiled)
        scan1_kernel<<<NB, SCAN_B, 0, g_aux.s2>>>();                      // 5
        scan2_kernel<<<1, 128, 0, g_aux.s2>>>();                          // 6
        scan3_kernel<<<NB, SCAN_B, 0, g_aux.s2>>>();                      // 7
        scatter_kernel<<<eblocks, 256, 0, g_aux.s2>>>(src, dst);          // 8
        cudaEventRecord(g_aux.join, g_aux.s2);
        cudaStreamWaitEvent(0, g_aux.join, 0);
    } else {
        zero_kernel<<<(NN + 255) / 256, 256>>>();
        hist_kernel<<<eblocks, 256>>>(dst);
        w1cvt_kernel<<<(IN_DIM * IN_DIM / 2 + 255) / 256, 256>>>(W1);
        gemm1_kernel<<<g1blocks, 512, G1_SMEM>>>(h, al1, ar1);
        scan1_kernel<<<NB, SCAN_B>>>();
        scan2_kernel<<<1, 128>>>();
        scan3_kernel<<<NB, SCAN_B>>>();
        scatter_kernel<<<eblocks, 256>>>(src, dst);
    }

    ew1_kernel<<<eblocks, 256>>>();
    agg1_kernel<<<nwarp_blocks, 256>>>(b1);
    gemm2_kernel<<<g2blocks, 256, G2_SMEM>>>(W2, al2, ar2);
    ew2_kernel<<<eblocks, 256>>>();
    agg2_kernel<<<nwarp_blocks, 256>>>(b2, out);
}

// round 17
// speedup vs baseline: 1.2932x; 1.1038x over previous
#include <cuda_runtime.h>
#include <cuda_fp16.h>
#include <string.h>

#define NN 100000
#define EE 1600000
#define IN_DIM 128
#define HID 32
#define HEADS 4
#define OUT_DIM 40
#define NEG_SLOPE 0.2f

#define G1_ROWS 128
#define A_STRIDE 136
#define G1_SMEM ((G1_ROWS*A_STRIDE + IN_DIM*A_STRIDE) * 2)   // 69632 B
#define G2_ROWS 128
#define B2_STRIDE 48
#define G2_SMEM ((G2_ROWS*A_STRIDE + IN_DIM*B2_STRIDE) * 2)  // 47104 B
#define SCAN_B 1024
#define NB ((NN + SCAN_B - 1) / SCAN_B)   // 98

typedef unsigned long long ull;
typedef unsigned int uint;

// ---------------- f32x2 packed-math helpers (sm_103a) ----------------
__device__ __forceinline__ ull pack2(float a, float b) {
    ull r; asm("mov.b64 %0,{%1,%2};" : "=l"(r) : "f"(a), "f"(b)); return r;
}
__device__ __forceinline__ void unpack2(ull p, float& a, float& b) {
    asm("mov.b64 {%0,%1},%2;" : "=f"(a), "=f"(b) : "l"(p));
}
__device__ __forceinline__ void ffma2(ull& acc, ull a, ull b) {
    asm("fma.rn.f32x2 %0,%1,%2,%0;" : "+l"(acc) : "l"(a), "l"(b));
}
// ---------------- fp16 bit-cast helpers ----------------
__device__ __forceinline__ uint f2_to_h2u(float a, float b) {
    __half2 h = __floats2half2_rn(a, b);
    uint u; memcpy(&u, &h, 4); return u;
}
__device__ __forceinline__ float2 h2u_to_f2(uint u) {
    __half2 h; memcpy(&h, &u, 4);
    return __half22float2(h);
}

// ---------------- scratch (device globals: allocation-free) ----------------
__device__ __half g_feat1h[NN * IN_DIM];
__device__ float  g_el1[NN * HEADS];
__device__ float  g_er1[NN * HEADS];
__device__ __half g_h1h[NN * IN_DIM];
__device__ __half g_feat2h[NN * OUT_DIM];
__device__ float  g_el2[NN];
__device__ float  g_er2[NN];
__device__ __half g_W1h[IN_DIM * IN_DIM];
__device__ int    g_deg[NN];
__device__ int    g_rank[EE];
__device__ int    g_rowptr[NN + 1];
__device__ int    g_esrc[EE];
__device__ int    g_bsum[128];
__device__ int    g_boff[128];

// ---------------- zero deg ----------------
__global__ void zero_kernel() {
    int i = blockIdx.x * blockDim.x + threadIdx.x;
    if (i < NN) g_deg[i] = 0;
}

// ---------------- W1 fp32 -> fp16 (once per launch) ----------------
__global__ void w1cvt_kernel(const float* __restrict__ W1) {
    int i = blockIdx.x * blockDim.x + threadIdx.x;
    if (i < IN_DIM * IN_DIM / 2) {
        float2 f = ((const float2*)W1)[i];
        ((__half2*)g_W1h)[i] = __floats2half2_rn(f.x, f.y);
    }
}

// ---- GEMM1 on tensor cores: 128-row tile, 512 thr, fused el1/er1, fp16 out ----
__global__ __launch_bounds__(512) void gemm1_kernel(const float* __restrict__ h,
                                                    const float* __restrict__ al1,
                                                    const float* __restrict__ ar1) {
    extern __shared__ __half smh[];
    __half* As = smh;                          // [128][A_STRIDE]
    __half* Ws = smh + G1_ROWS * A_STRIDE;     // [128][A_STRIDE]
    int t = threadIdx.x;
    int row0 = blockIdx.x * G1_ROWS;

    for (int i = t; i < IN_DIM * IN_DIM / 8; i += 512) {
        int r = i >> 4, c8 = i & 15;
        uint4 v = ((const uint4*)g_W1h)[i];
        *(uint4*)(Ws + r * A_STRIDE + c8 * 8) = v;
    }
    const float4* H4 = (const float4*)h;
    for (int i = t; i < G1_ROWS * IN_DIM / 4; i += 512) {
        int r = i >> 5, c4 = i & 31;
        int g = row0 + r;
        float4 f = (g < NN) ? H4[g * 32 + c4] : make_float4(0.f, 0.f, 0.f, 0.f);
        uint2 v;
        v.x = f2_to_h2u(f.x, f.y);
        v.y = f2_to_h2u(f.z, f.w);
        *(uint2*)(As + r * A_STRIDE + c4 * 4) = v;
    }
    __syncthreads();

    int w = t >> 5, lane = t & 31;
    int rw = (w & 7) * 16;
    int ch = (w >> 3) * 64;

    uint a_base = (uint)__cvta_generic_to_shared(
        As + (rw + (lane & 15)) * A_STRIDE + ((lane >> 4) * 8));
    uint b_base = (uint)__cvta_generic_to_shared(
        Ws + (lane & 15) * A_STRIDE + ch + ((lane >> 4) * 8));

    float acc[8][4];
    #pragma unroll
    for (int j = 0; j < 8; ++j)
        #pragma unroll
        for (int c = 0; c < 4; ++c) acc[j][c] = 0.f;

    #pragma unroll
    for (int kb = 0; kb < 8; ++kb) {
        uint a0, a1, a2, a3;
        asm volatile("ldmatrix.sync.aligned.m8n8.x4.shared.b16 {%0,%1,%2,%3}, [%4];"
                     : "=r"(a0), "=r"(a1), "=r"(a2), "=r"(a3)
                     : "r"(a_base + kb * 32));
        #pragma unroll
        for (int p = 0; p < 4; ++p) {
            uint b0, b1, b2, b3;
            asm volatile("ldmatrix.sync.aligned.m8n8.x4.trans.shared.b16 {%0,%1,%2,%3}, [%4];"
                         : "=r"(b0), "=r"(b1), "=r"(b2), "=r"(b3)
                         : "r"(b_base + kb * 16 * A_STRIDE * 2 + p * 32));
            asm volatile("mma.sync.aligned.m16n8k16.row.col.f32.f16.f16.f32 "
                         "{%0,%1,%2,%3}, {%4,%5,%6,%7}, {%8,%9}, {%0,%1,%2,%3};"
                         : "+f"(acc[2*p][0]), "+f"(acc[2*p][1]), "+f"(acc[2*p][2]), "+f"(acc[2*p][3])
                         : "r"(a0), "r"(a1), "r"(a2), "r"(a3), "r"(b0), "r"(b1));
            asm volatile("mma.sync.aligned.m16n8k16.row.col.f32.f16.f16.f32 "
                         "{%0,%1,%2,%3}, {%4,%5,%6,%7}, {%8,%9}, {%0,%1,%2,%3};"
                         : "+f"(acc[2*p+1][0]), "+f"(acc[2*p+1][1]), "+f"(acc[2*p+1][2]), "+f"(acc[2*p+1][3])
                         : "r"(a0), "r"(a1), "r"(a2), "r"(a3), "r"(b2), "r"(b3));
        }
    }

    int g0 = lane >> 2, quad = lane & 3;
    int r0g = row0 + rw + g0;
    int r1g = r0g + 8;
    int h0 = (w >> 3) * 2;

    float pe[2][2] = {{0.f, 0.f}, {0.f, 0.f}};
    float pr[2][2] = {{0.f, 0.f}, {0.f, 0.f}};

    #pragma unroll
    for (int j = 0; j < 8; ++j) {
        int n0 = ch + j * 8 + quad * 2;
        float2 av = *(const float2*)(al1 + n0);
        float2 rv = *(const float2*)(ar1 + n0);
        if (r0g < NN) ((uint*)g_feat1h)[(r0g * IN_DIM + n0) >> 1] = f2_to_h2u(acc[j][0], acc[j][1]);
        if (r1g < NN) ((uint*)g_feat1h)[(r1g * IN_DIM + n0) >> 1] = f2_to_h2u(acc[j][2], acc[j][3]);
        int hi = j >> 2;
        pe[hi][0] += acc[j][0] * av.x + acc[j][1] * av.y;
        pe[hi][1] += acc[j][2] * av.x + acc[j][3] * av.y;
        pr[hi][0] += acc[j][0] * rv.x + acc[j][1] * rv.y;
        pr[hi][1] += acc[j][2] * rv.x + acc[j][3] * rv.y;
    }
    #pragma unroll
    for (int hi = 0; hi < 2; ++hi)
        #pragma unroll
        for (int rr = 0; rr < 2; ++rr) {
            float e = pe[hi][rr], r = pr[hi][rr];
            e += __shfl_xor_sync(0xFFFFFFFFu, e, 1);
            e += __shfl_xor_sync(0xFFFFFFFFu, e, 2);
            r += __shfl_xor_sync(0xFFFFFFFFu, r, 1);
            r += __shfl_xor_sync(0xFFFFFFFFu, r, 2);
            int g = rr ? r1g : r0g;
            if (quad == 0 && g < NN) {
                g_el1[g * 4 + h0 + hi] = e;
                g_er1[g * 4 + h0 + hi] = r;
            }
        }
}

// ---------------- CSR build ----------------
__global__ void hist_kernel(const int* __restrict__ dst) {
    int i = blockIdx.x * blockDim.x + threadIdx.x;
    if (i < EE) g_rank[i] = atomicAdd(&g_deg[dst[i]], 1);
}

__global__ void scan1_kernel() {
    __shared__ int ws[32];
    int t = threadIdx.x;
    int lane = t & 31, wp = t >> 5;
    int i = blockIdx.x * SCAN_B + t;
    int v = (i < NN) ? g_deg[i] : 0;
    int x = v;
    #pragma unroll
    for (int off = 1; off < 32; off <<= 1) {
        int y = __shfl_up_sync(0xFFFFFFFFu, x, off);
        if (lane >= off) x += y;
    }
    if (lane == 31) ws[wp] = x;
    __syncthreads();
    if (wp == 0) {
        int o = ws[lane];
        int s = o;
        #pragma unroll
        for (int off = 1; off < 32; off <<= 1) {
            int y = __shfl_up_sync(0xFFFFFFFFu, s, off);
            if (lane >= off) s += y;
        }
        ws[lane] = s - o;
    }
    __syncthreads();
    int base = ws[wp];
    if (i < NN) g_rowptr[i] = x - v + base;
    if (t == SCAN_B - 1) g_bsum[blockIdx.x] = x + base;
}

__global__ void scan2_kernel() {
    int t = threadIdx.x;
    int lane = t & 31, wp = t >> 5;
    int v = (t < NB) ? g_bsum[t] : 0;
    int x = v;
    #pragma unroll
    for (int off = 1; off < 32; off <<= 1) {
        int y = __shfl_up_sync(0xFFFFFFFFu, x, off);
        if (lane >= off) x += y;
    }
    __shared__ int wsum[4];
    if (lane == 31) wsum[wp] = x;
    __syncthreads();
    int add = 0;
    for (int w = 0; w < wp; ++w) add += wsum[w];
    if (t < NB) g_boff[t] = x - v + add;
}

__global__ void scan3_kernel() {
    int i = blockIdx.x * SCAN_B + threadIdx.x;
    if (i < NN) g_rowptr[i] += g_boff[blockIdx.x];
    if (i == 0) g_rowptr[NN] = EE;
}

__global__ void scatter_kernel(const int* __restrict__ src, const int* __restrict__ dst) {
    int i = blockIdx.x * blockDim.x + threadIdx.x;
    if (i < EE) {
        int d = dst[i];
        g_esrc[g_rowptr[d] + g_rank[i]] = src[i];
    }
}

// ---- layer-1 aggregation: 2 nodes/warp (16 lanes x uint4), in-loop exp ----
__global__ __launch_bounds__(256) void agg1_kernel(const float* __restrict__ b1) {
    int gw = (blockIdx.x * blockDim.x + threadIdx.x) >> 5;
    int l = threadIdx.x & 31;
    int half = l >> 4, hl = l & 15;
    int n = gw * 2 + half;
    bool valid = n < NN;
    int hh = hl >> 2;                              // head of dims hl*8..hl*8+7
    float erh = valid ? g_er1[n * 4 + hh] : 0.f;
    int s0 = valid ? g_rowptr[n] : 0;
    int s1 = valid ? g_rowptr[n + 1] : 0;
    int tm = __reduce_max_sync(0xFFFFFFFFu, s1 - s0);

    const uint4* f4 = (const uint4*)g_feat1h;      // row = 16 uint4 (8 halfs each)
    ull aA0 = 0, aA1 = 0, aA2 = 0, aA3 = 0;
    ull aB0 = 0, aB1 = 0, aB2 = 0, aB3 = 0;
    float dsA = 0.f, dsB = 0.f;

    for (int t = 0; t < tm; t += 2) {
        int ia = s0 + t, ib = ia + 1;
        if (ia < s1) {
            int sa = g_esrc[ia];
            float ea = g_el1[sa * 4 + hh] + erh;
            ea = fmaxf(ea, NEG_SLOPE * ea);
            float wa = __expf(ea);
            uint4 fa = f4[sa * 16 + hl];
            ull w2 = pack2(wa, wa);
            float2 p;
            p = h2u_to_f2(fa.x); ffma2(aA0, w2, pack2(p.x, p.y));
            p = h2u_to_f2(fa.y); ffma2(aA1, w2, pack2(p.x, p.y));
            p = h2u_to_f2(fa.z); ffma2(aA2, w2, pack2(p.x, p.y));
            p = h2u_to_f2(fa.w); ffma2(aA3, w2, pack2(p.x, p.y));
            dsA += wa;
        }
        if (ib < s1) {
            int sb = g_esrc[ib];
            float eb = g_el1[sb * 4 + hh] + erh;
            eb = fmaxf(eb, NEG_SLOPE * eb);
            float wb = __expf(eb);
            uint4 fb = f4[sb * 16 + hl];
            ull w2 = pack2(wb, wb);
            float2 p;
            p = h2u_to_f2(fb.x); ffma2(aB0, w2, pack2(p.x, p.y));
            p = h2u_to_f2(fb.y); ffma2(aB1, w2, pack2(p.x, p.y));
            p = h2u_to_f2(fb.z); ffma2(aB2, w2, pack2(p.x, p.y));
            p = h2u_to_f2(fb.w); ffma2(aB3, w2, pack2(p.x, p.y));
            dsB += wb;
        }
    }

    if (!valid) return;
    float inv = 1.0f / fmaxf(dsA + dsB, 1e-9f);
    float4 bb0 = ((const float4*)b1)[hl * 2];
    float4 bb1 = ((const float4*)b1)[hl * 2 + 1];
    float xa, xb, ya, yb;
    uint4 o;
    unpack2(aA0, xa, ya); unpack2(aB0, xb, yb);
    o.x = f2_to_h2u(fmaxf((xa + xb) * inv + bb0.x, 0.f), fmaxf((ya + yb) * inv + bb0.y, 0.f));
    unpack2(aA1, xa, ya); unpack2(aB1, xb, yb);
    o.y = f2_to_h2u(fmaxf((xa + xb) * inv + bb0.z, 0.f), fmaxf((ya + yb) * inv + bb0.w, 0.f));
    unpack2(aA2, xa, ya); unpack2(aB2, xb, yb);
    o.z = f2_to_h2u(fmaxf((xa + xb) * inv + bb1.x, 0.f), fmaxf((ya + yb) * inv + bb1.y, 0.f));
    unpack2(aA3, xa, ya); unpack2(aB3, xb, yb);
    o.w = f2_to_h2u(fmaxf((xa + xb) * inv + bb1.z, 0.f), fmaxf((ya + yb) * inv + bb1.w, 0.f));
    ((uint4*)g_h1h)[n * 16 + hl] = o;
}

// ------- GEMM2 on tensor cores: 128-row tile, fused el2/er2, fp16 out -------
__global__ __launch_bounds__(256) void gemm2_kernel(const float* __restrict__ W2,
                                                    const float* __restrict__ al2,
                                                    const float* __restrict__ ar2) {
    extern __shared__ __half smh[];
    __half* As = smh;
    __half* Bs = smh + G2_ROWS * A_STRIDE;
    int t = threadIdx.x;
    int row0 = blockIdx.x * G2_ROWS;

    for (int i = t; i < G2_ROWS * IN_DIM / 8; i += 256) {
        int r = i >> 4, c8 = i & 15;
        int g = row0 + r;
        uint4 v = (g < NN) ? ((const uint4*)g_h1h)[g * 16 + c8]
                           : make_uint4(0u, 0u, 0u, 0u);
        *(uint4*)(As + r * A_STRIDE + c8 * 8) = v;
    }
    for (int i = t; i < IN_DIM * OUT_DIM; i += 256) {
        int r = i / OUT_DIM, c = i - r * OUT_DIM;
        Bs[r * B2_STRIDE + c] = __float2half_rn(W2[i]);
    }
    for (int i = t; i < IN_DIM * 8; i += 256) {
        int r = i >> 3, c = i & 7;
        Bs[r * B2_STRIDE + OUT_DIM + c] = __float2half_rn(0.f);
    }
    __syncthreads();

    int w = t >> 5, lane = t & 31;
    int rw = w * 16;

    uint a_base = (uint)__cvta_generic_to_shared(
        As + (rw + (lane & 15)) * A_STRIDE + ((lane >> 4) * 8));
    uint b_base = (uint)__cvta_generic_to_shared(
        Bs + (lane & 15) * B2_STRIDE + ((lane >> 4) * 8));

    float acc[6][4];
    #pragma unroll
    for (int j = 0; j < 6; ++j)
        #pragma unroll
        for (int c = 0; c < 4; ++c) acc[j][c] = 0.f;

    #pragma unroll
    for (int kb = 0; kb < 8; ++kb) {
        uint a0, a1, a2, a3;
        asm volatile("ldmatrix.sync.aligned.m8n8.x4.shared.b16 {%0,%1,%2,%3}, [%4];"
                     : "=r"(a0), "=r"(a1), "=r"(a2), "=r"(a3)
                     : "r"(a_base + kb * 32));
        #pragma unroll
        for (int p = 0; p < 3; ++p) {
            uint b0, b1, b2, b3;
            asm volatile("ldmatrix.sync.aligned.m8n8.x4.trans.shared.b16 {%0,%1,%2,%3}, [%4];"
                         : "=r"(b0), "=r"(b1), "=r"(b2), "=r"(b3)
                         : "r"(b_base + kb * 16 * B2_STRIDE * 2 + p * 32));
            asm volatile("mma.sync.aligned.m16n8k16.row.col.f32.f16.f16.f32 "
                         "{%0,%1,%2,%3}, {%4,%5,%6,%7}, {%8,%9}, {%0,%1,%2,%3};"
                         : "+f"(acc[2*p][0]), "+f"(acc[2*p][1]), "+f"(acc[2*p][2]), "+f"(acc[2*p][3])
                         : "r"(a0), "r"(a1), "r"(a2), "r"(a3), "r"(b0), "r"(b1));
            asm volatile("mma.sync.aligned.m16n8k16.row.col.f32.f16.f16.f32 "
                         "{%0,%1,%2,%3}, {%4,%5,%6,%7}, {%8,%9}, {%0,%1,%2,%3};"
                         : "+f"(acc[2*p+1][0]), "+f"(acc[2*p+1][1]), "+f"(acc[2*p+1][2]), "+f"(acc[2*p+1][3])
                         : "r"(a0), "r"(a1), "r"(a2), "r"(a3), "r"(b2), "r"(b3));
        }
    }

    int g0 = lane >> 2, quad = lane & 3;
    int r0g = row0 + rw + g0;
    int r1g = r0g + 8;

    float p0 = 0.f, p1 = 0.f, q0 = 0.f, q1 = 0.f;
    #pragma unroll
    for (int j = 0; j < 5; ++j) {
        int n0 = j * 8 + quad * 2;
        float2 av = *(const float2*)(al2 + n0);
        float2 rv = *(const float2*)(ar2 + n0);
        if (r0g < NN) ((uint*)g_feat2h)[(r0g * OUT_DIM + n0) >> 1] = f2_to_h2u(acc[j][0], acc[j][1]);
        if (r1g < NN) ((uint*)g_feat2h)[(r1g * OUT_DIM + n0) >> 1] = f2_to_h2u(acc[j][2], acc[j][3]);
        p0 += acc[j][0] * av.x + acc[j][1] * av.y;
        p1 += acc[j][2] * av.x + acc[j][3] * av.y;
        q0 += acc[j][0] * rv.x + acc[j][1] * rv.y;
        q1 += acc[j][2] * rv.x + acc[j][3] * rv.y;
    }
    #pragma unroll
    for (int off = 1; off <= 2; off <<= 1) {
        p0 += __shfl_xor_sync(0xFFFFFFFFu, p0, off);
        p1 += __shfl_xor_sync(0xFFFFFFFFu, p1, off);
        q0 += __shfl_xor_sync(0xFFFFFFFFu, q0, off);
        q1 += __shfl_xor_sync(0xFFFFFFFFu, q1, off);
    }
    if (quad == 0) {
        if (r0g < NN) { g_el2[r0g] = p0; g_er2[r0g] = q0; }
        if (r1g < NN) { g_el2[r1g] = p1; g_er2[r1g] = q1; }
    }
}

// ---- layer-2 aggregation: 6 nodes/warp (5 lanes x uint4), in-loop exp ----
__global__ __launch_bounds__(256) void agg2_kernel(const float* __restrict__ b2, float* __restrict__ out) {
    int gw = (blockIdx.x * blockDim.x + threadIdx.x) >> 5;
    int l = threadIdx.x & 31;
    int slot = l / 5;                 // 0..6 (lanes 30,31 -> 6 = inactive)
    int q = l - slot * 5;             // lane within slot, 0..4
    int n = gw * 6 + slot;
    bool valid = (slot < 6) && (n < NN);
    float er = valid ? g_er2[n] : 0.f;
    int s0 = valid ? g_rowptr[n] : 0;
    int s1 = valid ? g_rowptr[n + 1] : 0;
    int tm = __reduce_max_sync(0xFFFFFFFFu, s1 - s0);

    const uint4* f4 = (const uint4*)g_feat2h;     // row = 5 uint4 (8 halfs each)
    ull aA0 = 0, aA1 = 0, aA2 = 0, aA3 = 0;
    ull aB0 = 0, aB1 = 0, aB2 = 0, aB3 = 0;
    float dsA = 0.f, dsB = 0.f;

    for (int t = 0; t < tm; t += 2) {
        int ia = s0 + t, ib = ia + 1;
        if (ia < s1) {
            int sa = g_esrc[ia];
            float ea = g_el2[sa] + er;
            ea = fmaxf(ea, NEG_SLOPE * ea);
            float wa = __expf(ea);
            uint4 fa = f4[sa * 5 + q];
            ull w2 = pack2(wa, wa);
            float2 p;
            p = h2u_to_f2(fa.x); ffma2(aA0, w2, pack2(p.x, p.y));
            p = h2u_to_f2(fa.y); ffma2(aA1, w2, pack2(p.x, p.y));
            p = h2u_to_f2(fa.z); ffma2(aA2, w2, pack2(p.x, p.y));
            p = h2u_to_f2(fa.w); ffma2(aA3, w2, pack2(p.x, p.y));
            dsA += wa;
        }
        if (ib < s1) {
            int sb = g_esrc[ib];
            float eb = g_el2[sb] + er;
            eb = fmaxf(eb, NEG_SLOPE * eb);
            float wb = __expf(eb);
            uint4 fb = f4[sb * 5 + q];
            ull w2 = pack2(wb, wb);
            float2 p;
            p = h2u_to_f2(fb.x); ffma2(aB0, w2, pack2(p.x, p.y));
            p = h2u_to_f2(fb.y); ffma2(aB1, w2, pack2(p.x, p.y));
            p = h2u_to_f2(fb.z); ffma2(aB2, w2, pack2(p.x, p.y));
            p = h2u_to_f2(fb.w); ffma2(aB3, w2, pack2(p.x, p.y));
            dsB += wb;
        }
    }

    if (!valid) return;
    float inv = 1.0f / fmaxf(dsA + dsB, 1e-9f);
    float4 bb0 = ((const float4*)b2)[q * 2];
    float4 bb1 = ((const float4*)b2)[q * 2 + 1];
    float xa, xb, ya, yb;
    float4 o0, o1;
    unpack2(aA0, xa, ya); unpack2(aB0, xb, yb);
    o0.x = (xa + xb) * inv + bb0.x; o0.y = (ya + yb) * inv + bb0.y;
    unpack2(aA1, xa, ya); unpack2(aB1, xb, yb);
    o0.z = (xa + xb) * inv + bb0.z; o0.w = (ya + yb) * inv + bb0.w;
    unpack2(aA2, xa, ya); unpack2(aB2, xb, yb);
    o1.x = (xa + xb) * inv + bb1.x; o1.y = (ya + yb) * inv + bb1.y;
    unpack2(aA3, xa, ya); unpack2(aB3, xb, yb);
    o1.z = (xa + xb) * inv + bb1.z; o1.w = (ya + yb) * inv + bb1.w;
    ((float4*)out)[n * 10 + q * 2] = o0;
    ((float4*)out)[n * 10 + q * 2 + 1] = o1;
}

// ---------------- side stream for CSR/GEMM1 overlap ----------------
namespace {
struct Aux {
    cudaStream_t s2;
    cudaEvent_t fork, join;
    bool ok;
    Aux() : s2(nullptr), fork(nullptr), join(nullptr), ok(false) {
        if (cudaStreamCreateWithFlags(&s2, cudaStreamNonBlocking) != cudaSuccess) return;
        if (cudaEventCreateWithFlags(&fork, cudaEventDisableTiming) != cudaSuccess) return;
        if (cudaEventCreateWithFlags(&join, cudaEventDisableTiming) != cudaSuccess) return;
        ok = true;
    }
};
Aux g_aux;
}

// ---------------- launch ----------------
extern "C" void kernel_launch(void* const* d_in, const int* in_sizes, int n_in,
                              void* d_out, int out_size) {
    const float* h   = (const float*)d_in[0];
    const int*   src = (const int*)  d_in[1];
    const int*   dst = (const int*)  d_in[2];
    const float* W1  = (const float*)d_in[3];
    const float* al1 = (const float*)d_in[4];
    const float* ar1 = (const float*)d_in[5];
    const float* b1  = (const float*)d_in[6];
    const float* W2  = (const float*)d_in[7];
    const float* al2 = (const float*)d_in[8];
    const float* ar2 = (const float*)d_in[9];
    const float* b2  = (const float*)d_in[10];
    float* out = (float*)d_out;

    cudaFuncSetAttribute(gemm1_kernel, cudaFuncAttributeMaxDynamicSharedMemorySize, G1_SMEM);
    cudaFuncSetAttribute(gemm2_kernel, cudaFuncAttributeMaxDynamicSharedMemorySize, G2_SMEM);

    int eblocks = (EE + 255) / 256;
    int g1blocks = (NN + G1_ROWS - 1) / G1_ROWS;
    int g2blocks = (NN + G2_ROWS - 1) / G2_ROWS;
    int a1blocks = (NN + 15) / 16;    // 8 warps/block x 2 nodes/warp
    int a2blocks = (NN + 47) / 48;    // 8 warps/block x 6 nodes/warp

    if (g_aux.ok) {
        cudaEventRecord(g_aux.fork, 0);
        cudaStreamWaitEvent(g_aux.s2, g_aux.fork, 0);
        zero_kernel<<<(NN + 255) / 256, 256, 0, g_aux.s2>>>();            // 1
        hist_kernel<<<eblocks, 256, 0, g_aux.s2>>>(dst);                  // 2
        w1cvt_kernel<<<(IN_DIM * IN_DIM / 2 + 255) / 256, 256>>>(W1);     // 3 (main)
        gemm1_kernel<<<g1blocks, 512, G1_SMEM>>>(h, al1, ar1);            // 4 (main, profiled)
        scan1_kernel<<<NB, SCAN_B, 0, g_aux.s2>>>();                      // 5
        scan2_kernel<<<1, 128, 0, g_aux.s2>>>();                          // 6
        scan3_kernel<<<NB, SCAN_B, 0, g_aux.s2>>>();                      // 7
        scatter_kernel<<<eblocks, 256, 0, g_aux.s2>>>(src, dst);          // 8
        cudaEventRecord(g_aux.join, g_aux.s2);
        cudaStreamWaitEvent(0, g_aux.join, 0);
    } else {
        zero_kernel<<<(NN + 255) / 256, 256>>>();
        hist_kernel<<<eblocks, 256>>>(dst);
        w1cvt_kernel<<<(IN_DIM * IN_DIM / 2 + 255) / 256, 256>>>(W1);
        gemm1_kernel<<<g1blocks, 512, G1_SMEM>>>(h, al1, ar1);
        scan1_kernel<<<NB, SCAN_B>>>();
        scan2_kernel<<<1, 128>>>();
        scan3_kernel<<<NB, SCAN_B>>>();
        scatter_kernel<<<eblocks, 256>>>(src, dst);
    }

    agg1_kernel<<<a1blocks, 256>>>(b1);
    gemm2_kernel<<<g2blocks, 256, G2_SMEM>>>(W2, al2, ar2);
    agg2_kernel<<<a2blocks, 256>>>(b2, out);
}